// round 7
// baseline (speedup 1.0000x reference)
#include <cuda_runtime.h>
#include <cuda_bf16.h>
#include <cstdint>

#define N_NODES 100000
#define N_EDGES_MAX 1600000
#define D 512

// Static device scratch
__device__ float g_hp[(size_t)N_NODES * D];            // projected features (204.8 MB)
__device__ __nv_bfloat16 g_h_hi[(size_t)N_NODES * D];  // 102.4 MB
__device__ __nv_bfloat16 g_h_lo[(size_t)N_NODES * D];  // 102.4 MB
__device__ __nv_bfloat16 g_w_hi[D * D];                // transposed [n][k]
__device__ __nv_bfloat16 g_w_lo[D * D];                // transposed [n][k]
__device__ int   g_cur[N_NODES];
__device__ int   g_off[N_NODES];
__device__ int2  g_edge[N_EDGES_MAX];

__device__ __forceinline__ void mma_bf16(float c[4], const uint32_t a[4], const uint32_t b[2])
{
    asm volatile(
        "mma.sync.aligned.m16n8k16.row.col.f32.bf16.bf16.f32 "
        "{%0,%1,%2,%3}, {%4,%5,%6,%7}, {%8,%9}, {%0,%1,%2,%3};"
        : "+f"(c[0]), "+f"(c[1]), "+f"(c[2]), "+f"(c[3])
        : "r"(a[0]), "r"(a[1]), "r"(a[2]), "r"(a[3]), "r"(b[0]), "r"(b[1]));
}

#define CP_ASYNC16(dst_smem_u32, src_ptr) \
    asm volatile("cp.async.cg.shared.global [%0], [%1], 16;" \
                 :: "r"(dst_smem_u32), "l"(src_ptr))
#define CP_ASYNC_COMMIT() asm volatile("cp.async.commit_group;")
#define CP_ASYNC_WAIT0()  asm volatile("cp.async.wait_group 0;")

// ---------------------------------------------------------------------------
// Kernel 0a: split h -> (h_hi, h_lo) bf16, same [m][k] layout
// ---------------------------------------------------------------------------
__global__ __launch_bounds__(256) void convert_h_kernel(
    const float* __restrict__ h, size_t n_elems)
{
    size_t i = ((size_t)blockIdx.x * blockDim.x + threadIdx.x) * 4;
    size_t stride = (size_t)gridDim.x * blockDim.x * 4;
    for (; i < n_elems; i += stride) {
        float4 v = *reinterpret_cast<const float4*>(h + i);
        __nv_bfloat162 h01 = __floats2bfloat162_rn(v.x, v.y);
        __nv_bfloat162 h23 = __floats2bfloat162_rn(v.z, v.w);
        __nv_bfloat162 l01 = __floats2bfloat162_rn(v.x - __bfloat162float(h01.x),
                                                   v.y - __bfloat162float(h01.y));
        __nv_bfloat162 l23 = __floats2bfloat162_rn(v.z - __bfloat162float(h23.x),
                                                   v.w - __bfloat162float(h23.y));
        *reinterpret_cast<__nv_bfloat162*>(&g_h_hi[i])     = h01;
        *reinterpret_cast<__nv_bfloat162*>(&g_h_hi[i + 2]) = h23;
        *reinterpret_cast<__nv_bfloat162*>(&g_h_lo[i])     = l01;
        *reinterpret_cast<__nv_bfloat162*>(&g_h_lo[i + 2]) = l23;
    }
}

// ---------------------------------------------------------------------------
// Kernel 0b: split + transpose W -> (w_hi_T, w_lo_T) bf16 [n][k]
// ---------------------------------------------------------------------------
__global__ __launch_bounds__(256) void convert_w_kernel(const float* __restrict__ w)
{
    int i = blockIdx.x * blockDim.x + threadIdx.x;   // i = n*512 + k  (output idx)
    if (i >= D * D) return;
    int n = i >> 9;
    int k = i & 511;
    float v = w[(size_t)k * D + n];
    __nv_bfloat16 hi = __float2bfloat16_rn(v);
    __nv_bfloat16 lo = __float2bfloat16_rn(v - __bfloat162float(hi));
    g_w_hi[i] = hi;
    g_w_lo[i] = lo;
}

// ---------------------------------------------------------------------------
// Kernel 1: 3x-BF16 GEMM, presplit operands. hp[M,512] = h @ W
// BM=128, BN=64, BK=16. 8 warps (4x2), warp tile 32x32 (2x4 m16n8k16 frags).
// A smem [128][24] bf16 (k-major), B smem [64][24] bf16 (k-major, transposed).
// Inner loop: pure LDS + MMA (no conversions).
// ---------------------------------------------------------------------------
__global__ __launch_bounds__(256) void gemm_presplit_kernel(
    const __nv_bfloat16* __restrict__ h_hi,
    const __nv_bfloat16* __restrict__ h_lo,
    const __nv_bfloat16* __restrict__ w_hi,   // [n][k]
    const __nv_bfloat16* __restrict__ w_lo,   // [n][k]
    float* __restrict__ hp,
    int M)
{
    __shared__ __nv_bfloat16 As_hi[2][128][24];
    __shared__ __nv_bfloat16 As_lo[2][128][24];
    __shared__ __nv_bfloat16 Bs_hi[2][64][24];
    __shared__ __nv_bfloat16 Bs_lo[2][64][24];

    const int tid  = threadIdx.x;
    const int wid  = tid >> 5;
    const int lane = tid & 31;
    const int gid  = lane >> 2;     // 0..7
    const int tig  = lane & 3;      // 0..3

    const int warp_m = wid & 3;
    const int warp_n = wid >> 2;

    const int m0 = blockIdx.y * 128;
    const int n0 = blockIdx.x * 64;

    // cp.async mapping: 16B = 8 bf16 k-values
    const int arow = tid >> 1;            // 0..127
    const int akof = (tid & 1) * 8;       // 0 or 8
    const int gmA  = min(m0 + arow, M - 1);
    const bool bsel = (tid & 128) != 0;   // tid<128 -> hi, else lo
    const int  brow = (tid & 127) >> 1;   // 0..63 (n within tile)
    const int  bkof = (tid & 1) * 8;

    auto load_tile = [&](int stage, int kt) {
        const int kbase = kt * 16;
        uint32_t da = (uint32_t)__cvta_generic_to_shared(&As_hi[stage][arow][akof]);
        CP_ASYNC16(da, h_hi + (size_t)gmA * D + kbase + akof);
        uint32_t dl = (uint32_t)__cvta_generic_to_shared(&As_lo[stage][arow][akof]);
        CP_ASYNC16(dl, h_lo + (size_t)gmA * D + kbase + akof);
        const __nv_bfloat16* wsrc = bsel ? w_lo : w_hi;
        __nv_bfloat16* bdst = bsel ? &Bs_lo[stage][brow][bkof] : &Bs_hi[stage][brow][bkof];
        uint32_t db = (uint32_t)__cvta_generic_to_shared(bdst);
        CP_ASYNC16(db, wsrc + (size_t)(n0 + brow) * D + kbase + bkof);
        CP_ASYNC_COMMIT();
    };

    float c[2][4][4];
    #pragma unroll
    for (int mi = 0; mi < 2; mi++)
        #pragma unroll
        for (int ni = 0; ni < 4; ni++)
            #pragma unroll
            for (int r = 0; r < 4; r++) c[mi][ni][r] = 0.0f;

    load_tile(0, 0);
    CP_ASYNC_WAIT0();
    __syncthreads();

    const int NK = D / 16;   // 32
    #pragma unroll 1
    for (int kt = 0; kt < NK; kt++) {
        const int s = kt & 1;
        if (kt + 1 < NK) load_tile(s ^ 1, kt + 1);

        // A fragments: regs hold k-pairs (4B LDS each)
        uint32_t ah[2][4], al[2][4];
        #pragma unroll
        for (int mi = 0; mi < 2; mi++) {
            const int mb = warp_m * 32 + mi * 16;
            ah[mi][0] = *reinterpret_cast<const uint32_t*>(&As_hi[s][mb + gid    ][2 * tig    ]);
            ah[mi][1] = *reinterpret_cast<const uint32_t*>(&As_hi[s][mb + gid + 8][2 * tig    ]);
            ah[mi][2] = *reinterpret_cast<const uint32_t*>(&As_hi[s][mb + gid    ][2 * tig + 8]);
            ah[mi][3] = *reinterpret_cast<const uint32_t*>(&As_hi[s][mb + gid + 8][2 * tig + 8]);
            al[mi][0] = *reinterpret_cast<const uint32_t*>(&As_lo[s][mb + gid    ][2 * tig    ]);
            al[mi][1] = *reinterpret_cast<const uint32_t*>(&As_lo[s][mb + gid + 8][2 * tig    ]);
            al[mi][2] = *reinterpret_cast<const uint32_t*>(&As_lo[s][mb + gid    ][2 * tig + 8]);
            al[mi][3] = *reinterpret_cast<const uint32_t*>(&As_lo[s][mb + gid + 8][2 * tig + 8]);
        }
        // B fragments: col cb, k-pairs (4B LDS each; smem is k-contiguous)
        uint32_t bh[4][2], bl[4][2];
        #pragma unroll
        for (int ni = 0; ni < 4; ni++) {
            const int cb = warp_n * 32 + ni * 8 + gid;
            bh[ni][0] = *reinterpret_cast<const uint32_t*>(&Bs_hi[s][cb][2 * tig    ]);
            bh[ni][1] = *reinterpret_cast<const uint32_t*>(&Bs_hi[s][cb][2 * tig + 8]);
            bl[ni][0] = *reinterpret_cast<const uint32_t*>(&Bs_lo[s][cb][2 * tig    ]);
            bl[ni][1] = *reinterpret_cast<const uint32_t*>(&Bs_lo[s][cb][2 * tig + 8]);
        }

        #pragma unroll
        for (int mi = 0; mi < 2; mi++)
            #pragma unroll
            for (int ni = 0; ni < 4; ni++) {
                mma_bf16(c[mi][ni], ah[mi], bh[ni]);   // hi*hi
                mma_bf16(c[mi][ni], ah[mi], bl[ni]);   // hi*lo
                mma_bf16(c[mi][ni], al[mi], bh[ni]);   // lo*hi
            }

        CP_ASYNC_WAIT0();
        __syncthreads();
    }

    #pragma unroll
    for (int mi = 0; mi < 2; mi++) {
        #pragma unroll
        for (int ni = 0; ni < 4; ni++) {
            const int mrow = m0 + warp_m * 32 + mi * 16 + gid;
            const int ncol = n0 + warp_n * 32 + ni * 8 + tig * 2;
            if (mrow < M) {
                float2 v = make_float2(c[mi][ni][0], c[mi][ni][1]);
                *reinterpret_cast<float2*>(&hp[(size_t)mrow * D + ncol]) = v;
            }
            if (mrow + 8 < M) {
                float2 v = make_float2(c[mi][ni][2], c[mi][ni][3]);
                *reinterpret_cast<float2*>(&hp[(size_t)(mrow + 8) * D + ncol]) = v;
            }
        }
    }
}

// ---------------------------------------------------------------------------
// CSR build kernels
// ---------------------------------------------------------------------------
__global__ __launch_bounds__(256) void hist_kernel(const int* __restrict__ dst, int E)
{
    int i = blockIdx.x * blockDim.x + threadIdx.x;
    int stride = gridDim.x * blockDim.x;
    for (; i < E; i += stride)
        atomicAdd(&g_cur[dst[i]], 1);
}

__global__ __launch_bounds__(1024) void scan_kernel(int N)
{
    __shared__ int part[1024];
    const int t = threadIdx.x;
    const int chunk = (N + 1023) / 1024;
    const int begin = min(t * chunk, N);
    const int end   = min(begin + chunk, N);

    int sum = 0;
    for (int i = begin; i < end; i++) sum += g_cur[i];
    part[t] = sum;
    __syncthreads();

    #pragma unroll
    for (int s = 1; s < 1024; s <<= 1) {
        int v = (t >= s) ? part[t - s] : 0;
        __syncthreads();
        part[t] += v;
        __syncthreads();
    }

    int off = (t == 0) ? 0 : part[t - 1];
    for (int i = begin; i < end; i++) {
        int d = g_cur[i];
        g_off[i] = off;
        g_cur[i] = off;
        off += d;
    }
}

__global__ __launch_bounds__(256) void bucket_kernel(
    const int* __restrict__ src,
    const int* __restrict__ dst,
    const float* __restrict__ ew,
    int E)
{
    int i = blockIdx.x * blockDim.x + threadIdx.x;
    int stride = gridDim.x * blockDim.x;
    for (; i < E; i += stride) {
        int d = dst[i];
        int p = atomicAdd(&g_cur[d], 1);
        g_edge[p] = make_int2(src[i], __float_as_int(ew[i]));
    }
}

// ---------------------------------------------------------------------------
// Kernel 4: per-node gather-aggregate + fused ReLU.
// ---------------------------------------------------------------------------
__global__ __launch_bounds__(128) void aggregate_kernel(
    const float* __restrict__ hp,
    float* __restrict__ out,
    int N)
{
    const int n = blockIdx.x;
    if (n >= N) return;
    const int t = threadIdx.x;
    const int col = t * 4;

    int j  = g_off[n];
    const int je = g_cur[n];

    float4 acc0 = make_float4(0.f, 0.f, 0.f, 0.f);
    float4 acc1 = make_float4(0.f, 0.f, 0.f, 0.f);

    for (; j + 1 < je; j += 2) {
        int2 e0 = __ldg(&g_edge[j]);
        int2 e1 = __ldg(&g_edge[j + 1]);
        float w0 = __int_as_float(e0.y);
        float w1 = __int_as_float(e1.y);
        float4 v0 = *reinterpret_cast<const float4*>(hp + (size_t)e0.x * D + col);
        float4 v1 = *reinterpret_cast<const float4*>(hp + (size_t)e1.x * D + col);
        acc0.x += w0 * v0.x; acc0.y += w0 * v0.y; acc0.z += w0 * v0.z; acc0.w += w0 * v0.w;
        acc1.x += w1 * v1.x; acc1.y += w1 * v1.y; acc1.z += w1 * v1.z; acc1.w += w1 * v1.w;
    }
    if (j < je) {
        int2 e0 = __ldg(&g_edge[j]);
        float w0 = __int_as_float(e0.y);
        float4 v0 = *reinterpret_cast<const float4*>(hp + (size_t)e0.x * D + col);
        acc0.x += w0 * v0.x; acc0.y += w0 * v0.y; acc0.z += w0 * v0.z; acc0.w += w0 * v0.w;
    }

    float4 r;
    r.x = fmaxf(acc0.x + acc1.x, 0.f);
    r.y = fmaxf(acc0.y + acc1.y, 0.f);
    r.z = fmaxf(acc0.z + acc1.z, 0.f);
    r.w = fmaxf(acc0.w + acc1.w, 0.f);
    *reinterpret_cast<float4*>(out + (size_t)n * D + col) = r;
}

// ---------------------------------------------------------------------------
// Launch
// ---------------------------------------------------------------------------
extern "C" void kernel_launch(void* const* d_in, const int* in_sizes, int n_in,
                              void* d_out, int out_size)
{
    const float* h   = (const float*)d_in[0];
    const float* w   = (const float*)d_in[1];
    const float* ew  = (const float*)d_in[2];
    const int*   sv  = (const int*)d_in[3];
    const int*   dv  = (const int*)d_in[4];
    float* out       = (float*)d_out;

    const int M = in_sizes[0] / D;      // 100000
    const int E = in_sizes[2];          // 1600000

    static float* hp = nullptr;
    static int*   cur = nullptr;
    static __nv_bfloat16 *hhi = nullptr, *hlo = nullptr, *whi = nullptr, *wlo = nullptr;
    if (!hp)  cudaGetSymbolAddress((void**)&hp,  g_hp);
    if (!cur) cudaGetSymbolAddress((void**)&cur, g_cur);
    if (!hhi) cudaGetSymbolAddress((void**)&hhi, g_h_hi);
    if (!hlo) cudaGetSymbolAddress((void**)&hlo, g_h_lo);
    if (!whi) cudaGetSymbolAddress((void**)&whi, g_w_hi);
    if (!wlo) cudaGetSymbolAddress((void**)&wlo, g_w_lo);

    // 0) zero degree counters + presplit operands
    cudaMemsetAsync(cur, 0, (size_t)M * sizeof(int));
    size_t n_elems = (size_t)M * D;
    convert_h_kernel<<<148 * 16, 256>>>(h, n_elems);
    convert_w_kernel<<<(D * D + 255) / 256, 256>>>(w);

    // 1) hp = h @ W  (presplit 3x-BF16 tensor-core GEMM)
    dim3 ggrid(D / 64, (M + 127) / 128);
    gemm_presplit_kernel<<<ggrid, 256>>>(hhi, hlo, whi, wlo, hp, M);

    // 2) CSR build: histogram -> scan -> bucket
    int eblocks = min((E + 255) / 256, 148 * 8);
    hist_kernel<<<eblocks, 256>>>(dv, E);
    scan_kernel<<<1, 1024>>>(M);
    bucket_kernel<<<eblocks, 256>>>(sv, dv, ew, E);

    // 3) gather-aggregate + fused ReLU
    aggregate_kernel<<<M, 128>>>(hp, out, M);
}

// round 9
// speedup vs baseline: 1.1830x; 1.1830x over previous
#include <cuda_runtime.h>
#include <cuda_bf16.h>
#include <cuda_fp16.h>
#include <cstdint>

#define N_NODES 100000
#define N_EDGES_MAX 1600000
#define D 512

// Static device scratch
__device__ __half g_hp16[(size_t)N_NODES * D];    // projected features, fp16 (102.4 MB)
__device__ int   g_cur[N_NODES];                  // counts -> cursors -> end offsets
__device__ int   g_off[N_NODES];                  // start offsets
__device__ int2  g_edge[N_EDGES_MAX];             // CSR-ordered (src, edge_weight-bits)

// ---------------------------------------------------------------------------
// bf16 split helpers: x = hi + lo (both bf16); packs k-pairs into .b32
// ---------------------------------------------------------------------------
__device__ __forceinline__ void split_bf16x2(float x0, float x1, uint32_t& hi, uint32_t& lo)
{
    __nv_bfloat162 h = __floats2bfloat162_rn(x0, x1);
    float r0 = x0 - __bfloat162float(h.x);
    float r1 = x1 - __bfloat162float(h.y);
    __nv_bfloat162 l = __floats2bfloat162_rn(r0, r1);
    hi = reinterpret_cast<uint32_t&>(h);
    lo = reinterpret_cast<uint32_t&>(l);
}

__device__ __forceinline__ void mma_bf16(float c[4], const uint32_t a[4], const uint32_t b[2])
{
    asm volatile(
        "mma.sync.aligned.m16n8k16.row.col.f32.bf16.bf16.f32 "
        "{%0,%1,%2,%3}, {%4,%5,%6,%7}, {%8,%9}, {%0,%1,%2,%3};"
        : "+f"(c[0]), "+f"(c[1]), "+f"(c[2]), "+f"(c[3])
        : "r"(a[0]), "r"(a[1]), "r"(a[2]), "r"(a[3]), "r"(b[0]), "r"(b[1]));
}

#define CP_ASYNC16(dst_smem_u32, src_ptr) \
    asm volatile("cp.async.cg.shared.global [%0], [%1], 16;" \
                 :: "r"(dst_smem_u32), "l"(src_ptr))
#define CP_ASYNC_COMMIT() asm volatile("cp.async.commit_group;")
#define CP_ASYNC_WAIT0()  asm volatile("cp.async.wait_group 0;")

// ---------------------------------------------------------------------------
// Kernel 1: 3x-BF16 tensor-core GEMM  hp16[M,512] = fp16(h[M,512] @ W[512,512])
// Round-6 structure (best measured); epilogue stores __half2.
// ---------------------------------------------------------------------------
__global__ __launch_bounds__(256) void gemm_bf16x3_kernel(
    const float* __restrict__ h,
    const float* __restrict__ w,
    __half* __restrict__ hp,
    int M)
{
    __shared__ float As[2][128][24];
    __shared__ float Bs[2][16][68];

    const int tid  = threadIdx.x;
    const int wid  = tid >> 5;
    const int lane = tid & 31;
    const int gid  = lane >> 2;     // 0..7
    const int tig  = lane & 3;      // 0..3

    const int warp_m = wid & 3;
    const int warp_n = wid >> 2;

    const int m0 = blockIdx.y * 128;
    const int n0 = blockIdx.x * 64;

    const int arow = tid >> 2;          // 0..63
    const int acol = (tid & 3) * 4;     // 0,4,8,12
    const int brow = tid >> 4;          // 0..15
    const int bcol = (tid & 15) * 4;    // 0..60

    const int gmA0 = min(m0 + arow,      M - 1);
    const int gmA1 = min(m0 + arow + 64, M - 1);

    auto load_tile = [&](int stage, int kt) {
        const int kbase = kt * 16;
        uint32_t d0 = (uint32_t)__cvta_generic_to_shared(&As[stage][arow][acol]);
        uint32_t d1 = (uint32_t)__cvta_generic_to_shared(&As[stage][arow + 64][acol]);
        CP_ASYNC16(d0, h + (size_t)gmA0 * D + kbase + acol);
        CP_ASYNC16(d1, h + (size_t)gmA1 * D + kbase + acol);
        uint32_t d2 = (uint32_t)__cvta_generic_to_shared(&Bs[stage][brow][bcol]);
        CP_ASYNC16(d2, w + (size_t)(kbase + brow) * D + n0 + bcol);
        CP_ASYNC_COMMIT();
    };

    float c[2][4][4];
    #pragma unroll
    for (int mi = 0; mi < 2; mi++)
        #pragma unroll
        for (int ni = 0; ni < 4; ni++)
            #pragma unroll
            for (int r = 0; r < 4; r++) c[mi][ni][r] = 0.0f;

    load_tile(0, 0);
    CP_ASYNC_WAIT0();
    __syncthreads();

    const int NK = D / 16;   // 32
    #pragma unroll 1
    for (int kt = 0; kt < NK; kt++) {
        const int s = kt & 1;
        if (kt + 1 < NK) load_tile(s ^ 1, kt + 1);

        uint32_t ah[2][4], al[2][4];
        #pragma unroll
        for (int mi = 0; mi < 2; mi++) {
            const int mb = warp_m * 32 + mi * 16;
            float2 f0 = *reinterpret_cast<const float2*>(&As[s][mb + gid    ][2 * tig    ]);
            float2 f1 = *reinterpret_cast<const float2*>(&As[s][mb + gid + 8][2 * tig    ]);
            float2 f2 = *reinterpret_cast<const float2*>(&As[s][mb + gid    ][2 * tig + 8]);
            float2 f3 = *reinterpret_cast<const float2*>(&As[s][mb + gid + 8][2 * tig + 8]);
            split_bf16x2(f0.x, f0.y, ah[mi][0], al[mi][0]);
            split_bf16x2(f1.x, f1.y, ah[mi][1], al[mi][1]);
            split_bf16x2(f2.x, f2.y, ah[mi][2], al[mi][2]);
            split_bf16x2(f3.x, f3.y, ah[mi][3], al[mi][3]);
        }
        uint32_t bh[4][2], bl[4][2];
        #pragma unroll
        for (int ni = 0; ni < 4; ni++) {
            const int cb = warp_n * 32 + ni * 8 + gid;
            float v0 = Bs[s][2 * tig    ][cb];
            float v1 = Bs[s][2 * tig + 1][cb];
            float v2 = Bs[s][2 * tig + 8][cb];
            float v3 = Bs[s][2 * tig + 9][cb];
            split_bf16x2(v0, v1, bh[ni][0], bl[ni][0]);
            split_bf16x2(v2, v3, bh[ni][1], bl[ni][1]);
        }

        #pragma unroll
        for (int mi = 0; mi < 2; mi++)
            #pragma unroll
            for (int ni = 0; ni < 4; ni++) {
                mma_bf16(c[mi][ni], ah[mi], bh[ni]);   // hi*hi
                mma_bf16(c[mi][ni], ah[mi], bl[ni]);   // hi*lo
                mma_bf16(c[mi][ni], al[mi], bh[ni]);   // lo*hi
            }

        CP_ASYNC_WAIT0();
        __syncthreads();
    }

    // Epilogue: fp16 stores (half2 per c-pair)
    #pragma unroll
    for (int mi = 0; mi < 2; mi++) {
        #pragma unroll
        for (int ni = 0; ni < 4; ni++) {
            const int mrow = m0 + warp_m * 32 + mi * 16 + gid;
            const int ncol = n0 + warp_n * 32 + ni * 8 + tig * 2;
            if (mrow < M) {
                __half2 v = __floats2half2_rn(c[mi][ni][0], c[mi][ni][1]);
                *reinterpret_cast<__half2*>(&hp[(size_t)mrow * D + ncol]) = v;
            }
            if (mrow + 8 < M) {
                __half2 v = __floats2half2_rn(c[mi][ni][2], c[mi][ni][3]);
                *reinterpret_cast<__half2*>(&hp[(size_t)(mrow + 8) * D + ncol]) = v;
            }
        }
    }
}

// ---------------------------------------------------------------------------
// CSR build kernels
// ---------------------------------------------------------------------------
__global__ __launch_bounds__(256) void hist_kernel(const int* __restrict__ dst, int E)
{
    int i = blockIdx.x * blockDim.x + threadIdx.x;
    int stride = gridDim.x * blockDim.x;
    for (; i < E; i += stride)
        atomicAdd(&g_cur[dst[i]], 1);
}

__global__ __launch_bounds__(1024) void scan_kernel(int N)
{
    __shared__ int part[1024];
    const int t = threadIdx.x;
    const int chunk = (N + 1023) / 1024;
    const int begin = min(t * chunk, N);
    const int end   = min(begin + chunk, N);

    int sum = 0;
    for (int i = begin; i < end; i++) sum += g_cur[i];
    part[t] = sum;
    __syncthreads();

    #pragma unroll
    for (int s = 1; s < 1024; s <<= 1) {
        int v = (t >= s) ? part[t - s] : 0;
        __syncthreads();
        part[t] += v;
        __syncthreads();
    }

    int off = (t == 0) ? 0 : part[t - 1];
    for (int i = begin; i < end; i++) {
        int d = g_cur[i];
        g_off[i] = off;
        g_cur[i] = off;
        off += d;
    }
}

__global__ __launch_bounds__(256) void bucket_kernel(
    const int* __restrict__ src,
    const int* __restrict__ dst,
    const float* __restrict__ ew,
    int E)
{
    int i = blockIdx.x * blockDim.x + threadIdx.x;
    int stride = gridDim.x * blockDim.x;
    for (; i < E; i += stride) {
        int d = dst[i];
        int p = atomicAdd(&g_cur[d], 1);
        g_edge[p] = make_int2(src[i], __float_as_int(ew[i]));
    }
}

// ---------------------------------------------------------------------------
// Kernel 4: per-node fp16 gather-aggregate + fused ReLU.
// 128-thread block = 2 nodes x 64 threads; thread owns 8 cols (16B per edge).
// fp32 accumulation, dual dependency chains.
// ---------------------------------------------------------------------------
__global__ __launch_bounds__(128) void aggregate_f16_kernel(
    const __half* __restrict__ hp,
    float* __restrict__ out,
    int N)
{
    const int sub = threadIdx.x >> 6;            // 0/1: which node in block
    const int tt  = threadIdx.x & 63;            // 0..63
    const int n = blockIdx.x * 2 + sub;
    if (n >= N) return;
    const int col = tt * 8;

    int j  = g_off[n];
    const int je = g_cur[n];

    float a0[8] = {0.f,0.f,0.f,0.f,0.f,0.f,0.f,0.f};
    float a1[8] = {0.f,0.f,0.f,0.f,0.f,0.f,0.f,0.f};

    for (; j + 1 < je; j += 2) {
        int2 e0 = __ldg(&g_edge[j]);
        int2 e1 = __ldg(&g_edge[j + 1]);
        float w0 = __int_as_float(e0.y);
        float w1 = __int_as_float(e1.y);
        uint4 p0 = *reinterpret_cast<const uint4*>(hp + (size_t)e0.x * D + col);
        uint4 p1 = *reinterpret_cast<const uint4*>(hp + (size_t)e1.x * D + col);

        float2 f;
        f = __half22float2(*reinterpret_cast<__half2*>(&p0.x)); a0[0] += w0*f.x; a0[1] += w0*f.y;
        f = __half22float2(*reinterpret_cast<__half2*>(&p0.y)); a0[2] += w0*f.x; a0[3] += w0*f.y;
        f = __half22float2(*reinterpret_cast<__half2*>(&p0.z)); a0[4] += w0*f.x; a0[5] += w0*f.y;
        f = __half22float2(*reinterpret_cast<__half2*>(&p0.w)); a0[6] += w0*f.x; a0[7] += w0*f.y;
        f = __half22float2(*reinterpret_cast<__half2*>(&p1.x)); a1[0] += w1*f.x; a1[1] += w1*f.y;
        f = __half22float2(*reinterpret_cast<__half2*>(&p1.y)); a1[2] += w1*f.x; a1[3] += w1*f.y;
        f = __half22float2(*reinterpret_cast<__half2*>(&p1.z)); a1[4] += w1*f.x; a1[5] += w1*f.y;
        f = __half22float2(*reinterpret_cast<__half2*>(&p1.w)); a1[6] += w1*f.x; a1[7] += w1*f.y;
    }
    if (j < je) {
        int2 e0 = __ldg(&g_edge[j]);
        float w0 = __int_as_float(e0.y);
        uint4 p0 = *reinterpret_cast<const uint4*>(hp + (size_t)e0.x * D + col);
        float2 f;
        f = __half22float2(*reinterpret_cast<__half2*>(&p0.x)); a0[0] += w0*f.x; a0[1] += w0*f.y;
        f = __half22float2(*reinterpret_cast<__half2*>(&p0.y)); a0[2] += w0*f.x; a0[3] += w0*f.y;
        f = __half22float2(*reinterpret_cast<__half2*>(&p0.z)); a0[4] += w0*f.x; a0[5] += w0*f.y;
        f = __half22float2(*reinterpret_cast<__half2*>(&p0.w)); a0[6] += w0*f.x; a0[7] += w0*f.y;
    }

    float4 r0, r1;
    r0.x = fmaxf(a0[0] + a1[0], 0.f);
    r0.y = fmaxf(a0[1] + a1[1], 0.f);
    r0.z = fmaxf(a0[2] + a1[2], 0.f);
    r0.w = fmaxf(a0[3] + a1[3], 0.f);
    r1.x = fmaxf(a0[4] + a1[4], 0.f);
    r1.y = fmaxf(a0[5] + a1[5], 0.f);
    r1.z = fmaxf(a0[6] + a1[6], 0.f);
    r1.w = fmaxf(a0[7] + a1[7], 0.f);
    *reinterpret_cast<float4*>(out + (size_t)n * D + col)     = r0;
    *reinterpret_cast<float4*>(out + (size_t)n * D + col + 4) = r1;
}

// ---------------------------------------------------------------------------
// Launch
// ---------------------------------------------------------------------------
extern "C" void kernel_launch(void* const* d_in, const int* in_sizes, int n_in,
                              void* d_out, int out_size)
{
    const float* h   = (const float*)d_in[0];
    const float* w   = (const float*)d_in[1];
    const float* ew  = (const float*)d_in[2];
    const int*   sv  = (const int*)d_in[3];
    const int*   dv  = (const int*)d_in[4];
    float* out       = (float*)d_out;

    const int M = in_sizes[0] / D;      // 100000
    const int E = in_sizes[2];          // 1600000

    static __half* hp = nullptr;
    static int*    cur = nullptr;
    if (!hp)  cudaGetSymbolAddress((void**)&hp,  g_hp16);
    if (!cur) cudaGetSymbolAddress((void**)&cur, g_cur);

    // 0) zero degree counters
    cudaMemsetAsync(cur, 0, (size_t)M * sizeof(int));

    // 1) hp16 = fp16(h @ W)  (3x-BF16 tensor-core GEMM)
    dim3 ggrid(D / 64, (M + 127) / 128);
    gemm_bf16x3_kernel<<<ggrid, 256>>>(h, w, hp, M);

    // 2) CSR build: histogram -> scan -> bucket
    int eblocks = min((E + 255) / 256, 148 * 8);
    hist_kernel<<<eblocks, 256>>>(dv, E);
    scan_kernel<<<1, 1024>>>(M);
    bucket_kernel<<<eblocks, 256>>>(sv, dv, ew, E);

    // 3) fp16 gather-aggregate + fused ReLU (2 nodes per block)
    aggregate_f16_kernel<<<(M + 1) / 2, 128>>>(hp, out, M);
}

// round 10
// speedup vs baseline: 1.5468x; 1.3076x over previous
#include <cuda_runtime.h>
#include <cuda_bf16.h>
#include <cuda_fp16.h>
#include <cstdint>

#define N_NODES 100000
#define N_EDGES_MAX 1600000
#define D 512

// Static device scratch
__device__ __half g_hp16[(size_t)N_NODES * D];    // projected features, fp16 (102.4 MB)
__device__ int   g_cur[N_NODES];
__device__ int   g_off[N_NODES];
__device__ int2  g_edge[N_EDGES_MAX];

// ---------------------------------------------------------------------------
// tf32 helpers (round-to-nearest conversion; single-pass)
// ---------------------------------------------------------------------------
__device__ __forceinline__ uint32_t to_tf32(float x)
{
    uint32_t r;
    asm("cvt.rna.tf32.f32 %0, %1;" : "=r"(r) : "f"(x));
    return r;
}

__device__ __forceinline__ void mma_tf32(float c[4], const uint32_t a[4], const uint32_t b[2])
{
    asm volatile(
        "mma.sync.aligned.m16n8k8.row.col.f32.tf32.tf32.f32 "
        "{%0,%1,%2,%3}, {%4,%5,%6,%7}, {%8,%9}, {%0,%1,%2,%3};"
        : "+f"(c[0]), "+f"(c[1]), "+f"(c[2]), "+f"(c[3])
        : "r"(a[0]), "r"(a[1]), "r"(a[2]), "r"(a[3]), "r"(b[0]), "r"(b[1]));
}

#define CP_ASYNC16(dst_smem_u32, src_ptr) \
    asm volatile("cp.async.cg.shared.global [%0], [%1], 16;" \
                 :: "r"(dst_smem_u32), "l"(src_ptr))
#define CP_ASYNC_COMMIT() asm volatile("cp.async.commit_group;")
#define CP_ASYNC_WAIT0()  asm volatile("cp.async.wait_group 0;")

// ---------------------------------------------------------------------------
// Kernel 1: single-pass TF32 GEMM  hp16[M,512] = fp16(h[M,512] @ W[512,512])
// Round-4 validated skeleton: BM=128, BN=64, BK=16, 8 warps (4x2),
// warp tile 32x32 = 2x4 m16n8k8 frags, 2-stage cp.async. One mma per frag.
// ---------------------------------------------------------------------------
__global__ __launch_bounds__(256) void gemm_tf32_kernel(
    const float* __restrict__ h,
    const float* __restrict__ w,
    __half* __restrict__ hp,
    int M)
{
    __shared__ float As[2][128][20];
    __shared__ float Bs[2][16][72];

    const int tid  = threadIdx.x;
    const int wid  = tid >> 5;
    const int lane = tid & 31;
    const int gid  = lane >> 2;     // 0..7
    const int tig  = lane & 3;      // 0..3

    const int warp_m = wid & 3;
    const int warp_n = wid >> 2;

    const int m0 = blockIdx.y * 128;
    const int n0 = blockIdx.x * 64;

    const int arow = tid >> 2;          // 0..63
    const int acol = (tid & 3) * 4;     // 0,4,8,12
    const int brow = tid >> 4;          // 0..15
    const int bcol = (tid & 15) * 4;    // 0..60

    const int gmA0 = min(m0 + arow,      M - 1);
    const int gmA1 = min(m0 + arow + 64, M - 1);

    auto load_tile = [&](int stage, int kt) {
        const int kbase = kt * 16;
        uint32_t d0 = (uint32_t)__cvta_generic_to_shared(&As[stage][arow][acol]);
        uint32_t d1 = (uint32_t)__cvta_generic_to_shared(&As[stage][arow + 64][acol]);
        CP_ASYNC16(d0, h + (size_t)gmA0 * D + kbase + acol);
        CP_ASYNC16(d1, h + (size_t)gmA1 * D + kbase + acol);
        uint32_t d2 = (uint32_t)__cvta_generic_to_shared(&Bs[stage][brow][bcol]);
        CP_ASYNC16(d2, w + (size_t)(kbase + brow) * D + n0 + bcol);
        CP_ASYNC_COMMIT();
    };

    float c[2][4][4];
    #pragma unroll
    for (int mi = 0; mi < 2; mi++)
        #pragma unroll
        for (int ni = 0; ni < 4; ni++)
            #pragma unroll
            for (int r = 0; r < 4; r++) c[mi][ni][r] = 0.0f;

    load_tile(0, 0);
    CP_ASYNC_WAIT0();
    __syncthreads();

    const int NK = D / 16;   // 32
    #pragma unroll 1
    for (int kt = 0; kt < NK; kt++) {
        const int s = kt & 1;
        if (kt + 1 < NK) load_tile(s ^ 1, kt + 1);

        #pragma unroll
        for (int ks = 0; ks < 2; ks++) {
            const int k0 = ks * 8;

            uint32_t a[2][4];
            #pragma unroll
            for (int mi = 0; mi < 2; mi++) {
                const int mb = warp_m * 32 + mi * 16;
                a[mi][0] = to_tf32(As[s][mb + gid    ][k0 + tig    ]);
                a[mi][1] = to_tf32(As[s][mb + gid + 8][k0 + tig    ]);
                a[mi][2] = to_tf32(As[s][mb + gid    ][k0 + tig + 4]);
                a[mi][3] = to_tf32(As[s][mb + gid + 8][k0 + tig + 4]);
            }
            uint32_t b[4][2];
            #pragma unroll
            for (int ni = 0; ni < 4; ni++) {
                const int nb = warp_n * 32 + ni * 8;
                b[ni][0] = to_tf32(Bs[s][k0 + tig    ][nb + gid]);
                b[ni][1] = to_tf32(Bs[s][k0 + tig + 4][nb + gid]);
            }

            #pragma unroll
            for (int mi = 0; mi < 2; mi++)
                #pragma unroll
                for (int ni = 0; ni < 4; ni++)
                    mma_tf32(c[mi][ni], a[mi], b[ni]);
        }

        CP_ASYNC_WAIT0();
        __syncthreads();
    }

    // Epilogue: fp16 stores (half2 per c-pair)
    #pragma unroll
    for (int mi = 0; mi < 2; mi++) {
        #pragma unroll
        for (int ni = 0; ni < 4; ni++) {
            const int mrow = m0 + warp_m * 32 + mi * 16 + gid;
            const int ncol = n0 + warp_n * 32 + ni * 8 + tig * 2;
            if (mrow < M) {
                __half2 v = __floats2half2_rn(c[mi][ni][0], c[mi][ni][1]);
                *reinterpret_cast<__half2*>(&hp[(size_t)mrow * D + ncol]) = v;
            }
            if (mrow + 8 < M) {
                __half2 v = __floats2half2_rn(c[mi][ni][2], c[mi][ni][3]);
                *reinterpret_cast<__half2*>(&hp[(size_t)(mrow + 8) * D + ncol]) = v;
            }
        }
    }
}

// ---------------------------------------------------------------------------
// CSR build kernels
// ---------------------------------------------------------------------------
__global__ __launch_bounds__(256) void hist_kernel(const int* __restrict__ dst, int E)
{
    int i = blockIdx.x * blockDim.x + threadIdx.x;
    int stride = gridDim.x * blockDim.x;
    for (; i < E; i += stride)
        atomicAdd(&g_cur[dst[i]], 1);
}

__global__ __launch_bounds__(1024) void scan_kernel(int N)
{
    __shared__ int part[1024];
    const int t = threadIdx.x;
    const int chunk = (N + 1023) / 1024;
    const int begin = min(t * chunk, N);
    const int end   = min(begin + chunk, N);

    int sum = 0;
    for (int i = begin; i < end; i++) sum += g_cur[i];
    part[t] = sum;
    __syncthreads();

    #pragma unroll
    for (int s = 1; s < 1024; s <<= 1) {
        int v = (t >= s) ? part[t - s] : 0;
        __syncthreads();
        part[t] += v;
        __syncthreads();
    }

    int off = (t == 0) ? 0 : part[t - 1];
    for (int i = begin; i < end; i++) {
        int d = g_cur[i];
        g_off[i] = off;
        g_cur[i] = off;
        off += d;
    }
}

__global__ __launch_bounds__(256) void bucket_kernel(
    const int* __restrict__ src,
    const int* __restrict__ dst,
    const float* __restrict__ ew,
    int E)
{
    int i = blockIdx.x * blockDim.x + threadIdx.x;
    int stride = gridDim.x * blockDim.x;
    for (; i < E; i += stride) {
        int d = dst[i];
        int p = atomicAdd(&g_cur[d], 1);
        g_edge[p] = make_int2(src[i], __float_as_int(ew[i]));
    }
}

// ---------------------------------------------------------------------------
// Kernel 4: per-node fp16 gather-aggregate + fused ReLU.
// 128-thread block = 2 nodes x 64 threads; thread owns 8 cols (16B per edge).
// ---------------------------------------------------------------------------
__global__ __launch_bounds__(128) void aggregate_f16_kernel(
    const __half* __restrict__ hp,
    float* __restrict__ out,
    int N)
{
    const int sub = threadIdx.x >> 6;
    const int tt  = threadIdx.x & 63;
    const int n = blockIdx.x * 2 + sub;
    if (n >= N) return;
    const int col = tt * 8;

    int j  = g_off[n];
    const int je = g_cur[n];

    float a0[8] = {0.f,0.f,0.f,0.f,0.f,0.f,0.f,0.f};
    float a1[8] = {0.f,0.f,0.f,0.f,0.f,0.f,0.f,0.f};

    for (; j + 1 < je; j += 2) {
        int2 e0 = __ldg(&g_edge[j]);
        int2 e1 = __ldg(&g_edge[j + 1]);
        float w0 = __int_as_float(e0.y);
        float w1 = __int_as_float(e1.y);
        uint4 p0 = *reinterpret_cast<const uint4*>(hp + (size_t)e0.x * D + col);
        uint4 p1 = *reinterpret_cast<const uint4*>(hp + (size_t)e1.x * D + col);

        float2 f;
        f = __half22float2(*reinterpret_cast<__half2*>(&p0.x)); a0[0] += w0*f.x; a0[1] += w0*f.y;
        f = __half22float2(*reinterpret_cast<__half2*>(&p0.y)); a0[2] += w0*f.x; a0[3] += w0*f.y;
        f = __half22float2(*reinterpret_cast<__half2*>(&p0.z)); a0[4] += w0*f.x; a0[5] += w0*f.y;
        f = __half22float2(*reinterpret_cast<__half2*>(&p0.w)); a0[6] += w0*f.x; a0[7] += w0*f.y;
        f = __half22float2(*reinterpret_cast<__half2*>(&p1.x)); a1[0] += w1*f.x; a1[1] += w1*f.y;
        f = __half22float2(*reinterpret_cast<__half2*>(&p1.y)); a1[2] += w1*f.x; a1[3] += w1*f.y;
        f = __half22float2(*reinterpret_cast<__half2*>(&p1.z)); a1[4] += w1*f.x; a1[5] += w1*f.y;
        f = __half22float2(*reinterpret_cast<__half2*>(&p1.w)); a1[6] += w1*f.x; a1[7] += w1*f.y;
    }
    if (j < je) {
        int2 e0 = __ldg(&g_edge[j]);
        float w0 = __int_as_float(e0.y);
        uint4 p0 = *reinterpret_cast<const uint4*>(hp + (size_t)e0.x * D + col);
        float2 f;
        f = __half22float2(*reinterpret_cast<__half2*>(&p0.x)); a0[0] += w0*f.x; a0[1] += w0*f.y;
        f = __half22float2(*reinterpret_cast<__half2*>(&p0.y)); a0[2] += w0*f.x; a0[3] += w0*f.y;
        f = __half22float2(*reinterpret_cast<__half2*>(&p0.z)); a0[4] += w0*f.x; a0[5] += w0*f.y;
        f = __half22float2(*reinterpret_cast<__half2*>(&p0.w)); a0[6] += w0*f.x; a0[7] += w0*f.y;
    }

    float4 r0, r1;
    r0.x = fmaxf(a0[0] + a1[0], 0.f);
    r0.y = fmaxf(a0[1] + a1[1], 0.f);
    r0.z = fmaxf(a0[2] + a1[2], 0.f);
    r0.w = fmaxf(a0[3] + a1[3], 0.f);
    r1.x = fmaxf(a0[4] + a1[4], 0.f);
    r1.y = fmaxf(a0[5] + a1[5], 0.f);
    r1.z = fmaxf(a0[6] + a1[6], 0.f);
    r1.w = fmaxf(a0[7] + a1[7], 0.f);
    *reinterpret_cast<float4*>(out + (size_t)n * D + col)     = r0;
    *reinterpret_cast<float4*>(out + (size_t)n * D + col + 4) = r1;
}

// ---------------------------------------------------------------------------
// Launch
// ---------------------------------------------------------------------------
extern "C" void kernel_launch(void* const* d_in, const int* in_sizes, int n_in,
                              void* d_out, int out_size)
{
    const float* h   = (const float*)d_in[0];
    const float* w   = (const float*)d_in[1];
    const float* ew  = (const float*)d_in[2];
    const int*   sv  = (const int*)d_in[3];
    const int*   dv  = (const int*)d_in[4];
    float* out       = (float*)d_out;

    const int M = in_sizes[0] / D;      // 100000
    const int E = in_sizes[2];          // 1600000

    static __half* hp = nullptr;
    static int*    cur = nullptr;
    if (!hp)  cudaGetSymbolAddress((void**)&hp,  g_hp16);
    if (!cur) cudaGetSymbolAddress((void**)&cur, g_cur);

    // 0) zero degree counters
    cudaMemsetAsync(cur, 0, (size_t)M * sizeof(int));

    // 1) hp16 = fp16(h @ W)  (single-pass TF32 tensor-core GEMM)
    dim3 ggrid(D / 64, (M + 127) / 128);
    gemm_tf32_kernel<<<ggrid, 256>>>(h, w, hp, M);

    // 2) CSR build: histogram -> scan -> bucket
    int eblocks = min((E + 255) / 256, 148 * 8);
    hist_kernel<<<eblocks, 256>>>(dv, E);
    scan_kernel<<<1, 1024>>>(M);
    bucket_kernel<<<eblocks, 256>>>(sv, dv, ew, E);

    // 3) fp16 gather-aggregate + fused ReLU (2 nodes per block)
    aggregate_f16_kernel<<<(M + 1) / 2, 128>>>(hp, out, M);
}

// round 11
// speedup vs baseline: 1.5866x; 1.0257x over previous
#include <cuda_runtime.h>
#include <cuda_bf16.h>
#include <cuda_fp16.h>
#include <cstdint>

#define N_NODES 100000
#define N_EDGES_MAX 1600000
#define D 512

// Static device scratch
__device__ __half   g_hp16[(size_t)N_NODES * D];  // projected features fp16 (102.4 MB)
__device__ uint32_t g_wt[D * D];                  // W as tf32 bit patterns, [k][n] (1 MB)
__device__ int   g_cur[N_NODES];
__device__ int   g_off[N_NODES];
__device__ int2  g_edge[N_EDGES_MAX];

// ---------------------------------------------------------------------------
// tf32 helpers
// ---------------------------------------------------------------------------
__device__ __forceinline__ uint32_t to_tf32(float x)
{
    uint32_t r;
    asm("cvt.rna.tf32.f32 %0, %1;" : "=r"(r) : "f"(x));
    return r;
}

__device__ __forceinline__ void mma_tf32(float c[4], const uint32_t a[4], const uint32_t b[2])
{
    asm volatile(
        "mma.sync.aligned.m16n8k8.row.col.f32.tf32.tf32.f32 "
        "{%0,%1,%2,%3}, {%4,%5,%6,%7}, {%8,%9}, {%0,%1,%2,%3};"
        : "+f"(c[0]), "+f"(c[1]), "+f"(c[2]), "+f"(c[3])
        : "r"(a[0]), "r"(a[1]), "r"(a[2]), "r"(a[3]), "r"(b[0]), "r"(b[1]));
}

#define CP_ASYNC16(dst_smem_u32, src_ptr) \
    asm volatile("cp.async.cg.shared.global [%0], [%1], 16;" \
                 :: "r"(dst_smem_u32), "l"(src_ptr))
#define CP_ASYNC_COMMIT() asm volatile("cp.async.commit_group;")
#define CP_ASYNC_WAIT0()  asm volatile("cp.async.wait_group 0;")

// ---------------------------------------------------------------------------
// Kernel 0: W -> tf32 bit patterns (same layout, run once per call; 1 MB)
// ---------------------------------------------------------------------------
__global__ __launch_bounds__(256) void convert_w_kernel(const float* __restrict__ w)
{
    int i = blockIdx.x * blockDim.x + threadIdx.x;
    if (i < D * D) g_wt[i] = to_tf32(w[i]);
}

// ---------------------------------------------------------------------------
// Kernel 1: single-pass TF32 GEMM  hp16[M,512] = fp16(h[M,512] @ W[512,512])
// B operand pre-converted (g_wt); only A converts in-kernel.
// ---------------------------------------------------------------------------
__global__ __launch_bounds__(256) void gemm_tf32_kernel(
    const float* __restrict__ h,
    const uint32_t* __restrict__ wt,
    __half* __restrict__ hp,
    int M)
{
    __shared__ float    As[2][128][20];
    __shared__ uint32_t Bs[2][16][72];

    const int tid  = threadIdx.x;
    const int wid  = tid >> 5;
    const int lane = tid & 31;
    const int gid  = lane >> 2;     // 0..7
    const int tig  = lane & 3;      // 0..3

    const int warp_m = wid & 3;
    const int warp_n = wid >> 2;

    const int m0 = blockIdx.y * 128;
    const int n0 = blockIdx.x * 64;

    const int arow = tid >> 2;          // 0..63
    const int acol = (tid & 3) * 4;     // 0,4,8,12
    const int brow = tid >> 4;          // 0..15
    const int bcol = (tid & 15) * 4;    // 0..60

    const int gmA0 = min(m0 + arow,      M - 1);
    const int gmA1 = min(m0 + arow + 64, M - 1);

    auto load_tile = [&](int stage, int kt) {
        const int kbase = kt * 16;
        uint32_t d0 = (uint32_t)__cvta_generic_to_shared(&As[stage][arow][acol]);
        uint32_t d1 = (uint32_t)__cvta_generic_to_shared(&As[stage][arow + 64][acol]);
        CP_ASYNC16(d0, h + (size_t)gmA0 * D + kbase + acol);
        CP_ASYNC16(d1, h + (size_t)gmA1 * D + kbase + acol);
        uint32_t d2 = (uint32_t)__cvta_generic_to_shared(&Bs[stage][brow][bcol]);
        CP_ASYNC16(d2, wt + (size_t)(kbase + brow) * D + n0 + bcol);
        CP_ASYNC_COMMIT();
    };

    float c[2][4][4];
    #pragma unroll
    for (int mi = 0; mi < 2; mi++)
        #pragma unroll
        for (int ni = 0; ni < 4; ni++)
            #pragma unroll
            for (int r = 0; r < 4; r++) c[mi][ni][r] = 0.0f;

    load_tile(0, 0);
    CP_ASYNC_WAIT0();
    __syncthreads();

    const int NK = D / 16;   // 32
    #pragma unroll 1
    for (int kt = 0; kt < NK; kt++) {
        const int s = kt & 1;
        if (kt + 1 < NK) load_tile(s ^ 1, kt + 1);

        #pragma unroll
        for (int ks = 0; ks < 2; ks++) {
            const int k0 = ks * 8;

            uint32_t a[2][4];
            #pragma unroll
            for (int mi = 0; mi < 2; mi++) {
                const int mb = warp_m * 32 + mi * 16;
                a[mi][0] = to_tf32(As[s][mb + gid    ][k0 + tig    ]);
                a[mi][1] = to_tf32(As[s][mb + gid + 8][k0 + tig    ]);
                a[mi][2] = to_tf32(As[s][mb + gid    ][k0 + tig + 4]);
                a[mi][3] = to_tf32(As[s][mb + gid + 8][k0 + tig + 4]);
            }
            uint32_t b[4][2];
            #pragma unroll
            for (int ni = 0; ni < 4; ni++) {
                const int nb = warp_n * 32 + ni * 8;
                b[ni][0] = Bs[s][k0 + tig    ][nb + gid];
                b[ni][1] = Bs[s][k0 + tig + 4][nb + gid];
            }

            #pragma unroll
            for (int mi = 0; mi < 2; mi++)
                #pragma unroll
                for (int ni = 0; ni < 4; ni++)
                    mma_tf32(c[mi][ni], a[mi], b[ni]);
        }

        CP_ASYNC_WAIT0();
        __syncthreads();
    }

    // Epilogue: fp16 stores
    #pragma unroll
    for (int mi = 0; mi < 2; mi++) {
        #pragma unroll
        for (int ni = 0; ni < 4; ni++) {
            const int mrow = m0 + warp_m * 32 + mi * 16 + gid;
            const int ncol = n0 + warp_n * 32 + ni * 8 + tig * 2;
            if (mrow < M) {
                __half2 v = __floats2half2_rn(c[mi][ni][0], c[mi][ni][1]);
                *reinterpret_cast<__half2*>(&hp[(size_t)mrow * D + ncol]) = v;
            }
            if (mrow + 8 < M) {
                __half2 v = __floats2half2_rn(c[mi][ni][2], c[mi][ni][3]);
                *reinterpret_cast<__half2*>(&hp[(size_t)(mrow + 8) * D + ncol]) = v;
            }
        }
    }
}

// ---------------------------------------------------------------------------
// CSR build kernels
// ---------------------------------------------------------------------------
__global__ __launch_bounds__(256) void hist_kernel(const int* __restrict__ dst, int E)
{
    int i = blockIdx.x * blockDim.x + threadIdx.x;
    int stride = gridDim.x * blockDim.x;
    for (; i < E; i += stride)
        atomicAdd(&g_cur[dst[i]], 1);
}

__global__ __launch_bounds__(1024) void scan_kernel(int N)
{
    __shared__ int part[1024];
    const int t = threadIdx.x;
    const int chunk = (N + 1023) / 1024;
    const int begin = min(t * chunk, N);
    const int end   = min(begin + chunk, N);

    int sum = 0;
    for (int i = begin; i < end; i++) sum += g_cur[i];
    part[t] = sum;
    __syncthreads();

    #pragma unroll
    for (int s = 1; s < 1024; s <<= 1) {
        int v = (t >= s) ? part[t - s] : 0;
        __syncthreads();
        part[t] += v;
        __syncthreads();
    }

    int off = (t == 0) ? 0 : part[t - 1];
    for (int i = begin; i < end; i++) {
        int d = g_cur[i];
        g_off[i] = off;
        g_cur[i] = off;
        off += d;
    }
}

__global__ __launch_bounds__(256) void bucket_kernel(
    const int* __restrict__ src,
    const int* __restrict__ dst,
    const float* __restrict__ ew,
    int E)
{
    int i = blockIdx.x * blockDim.x + threadIdx.x;
    int stride = gridDim.x * blockDim.x;
    for (; i < E; i += stride) {
        int d = dst[i];
        int p = atomicAdd(&g_cur[d], 1);
        g_edge[p] = make_int2(src[i], __float_as_int(ew[i]));
    }
}

// ---------------------------------------------------------------------------
// Kernel 4: per-node fp16 gather-aggregate + fused ReLU.
// ---------------------------------------------------------------------------
__global__ __launch_bounds__(128) void aggregate_f16_kernel(
    const __half* __restrict__ hp,
    float* __restrict__ out,
    int N)
{
    const int sub = threadIdx.x >> 6;
    const int tt  = threadIdx.x & 63;
    const int n = blockIdx.x * 2 + sub;
    if (n >= N) return;
    const int col = tt * 8;

    int j  = g_off[n];
    const int je = g_cur[n];

    float a0[8] = {0.f,0.f,0.f,0.f,0.f,0.f,0.f,0.f};
    float a1[8] = {0.f,0.f,0.f,0.f,0.f,0.f,0.f,0.f};

    for (; j + 1 < je; j += 2) {
        int2 e0 = __ldg(&g_edge[j]);
        int2 e1 = __ldg(&g_edge[j + 1]);
        float w0 = __int_as_float(e0.y);
        float w1 = __int_as_float(e1.y);
        uint4 p0 = *reinterpret_cast<const uint4*>(hp + (size_t)e0.x * D + col);
        uint4 p1 = *reinterpret_cast<const uint4*>(hp + (size_t)e1.x * D + col);

        float2 f;
        f = __half22float2(*reinterpret_cast<__half2*>(&p0.x)); a0[0] += w0*f.x; a0[1] += w0*f.y;
        f = __half22float2(*reinterpret_cast<__half2*>(&p0.y)); a0[2] += w0*f.x; a0[3] += w0*f.y;
        f = __half22float2(*reinterpret_cast<__half2*>(&p0.z)); a0[4] += w0*f.x; a0[5] += w0*f.y;
        f = __half22float2(*reinterpret_cast<__half2*>(&p0.w)); a0[6] += w0*f.x; a0[7] += w0*f.y;
        f = __half22float2(*reinterpret_cast<__half2*>(&p1.x)); a1[0] += w1*f.x; a1[1] += w1*f.y;
        f = __half22float2(*reinterpret_cast<__half2*>(&p1.y)); a1[2] += w1*f.x; a1[3] += w1*f.y;
        f = __half22float2(*reinterpret_cast<__half2*>(&p1.z)); a1[4] += w1*f.x; a1[5] += w1*f.y;
        f = __half22float2(*reinterpret_cast<__half2*>(&p1.w)); a1[6] += w1*f.x; a1[7] += w1*f.y;
    }
    if (j < je) {
        int2 e0 = __ldg(&g_edge[j]);
        float w0 = __int_as_float(e0.y);
        uint4 p0 = *reinterpret_cast<const uint4*>(hp + (size_t)e0.x * D + col);
        float2 f;
        f = __half22float2(*reinterpret_cast<__half2*>(&p0.x)); a0[0] += w0*f.x; a0[1] += w0*f.y;
        f = __half22float2(*reinterpret_cast<__half2*>(&p0.y)); a0[2] += w0*f.x; a0[3] += w0*f.y;
        f = __half22float2(*reinterpret_cast<__half2*>(&p0.z)); a0[4] += w0*f.x; a0[5] += w0*f.y;
        f = __half22float2(*reinterpret_cast<__half2*>(&p0.w)); a0[6] += w0*f.x; a0[7] += w0*f.y;
    }

    float4 r0, r1;
    r0.x = fmaxf(a0[0] + a1[0], 0.f);
    r0.y = fmaxf(a0[1] + a1[1], 0.f);
    r0.z = fmaxf(a0[2] + a1[2], 0.f);
    r0.w = fmaxf(a0[3] + a1[3], 0.f);
    r1.x = fmaxf(a0[4] + a1[4], 0.f);
    r1.y = fmaxf(a0[5] + a1[5], 0.f);
    r1.z = fmaxf(a0[6] + a1[6], 0.f);
    r1.w = fmaxf(a0[7] + a1[7], 0.f);
    *reinterpret_cast<float4*>(out + (size_t)n * D + col)     = r0;
    *reinterpret_cast<float4*>(out + (size_t)n * D + col + 4) = r1;
}

// ---------------------------------------------------------------------------
// Launch — graph-parallel: [convert_w -> GEMM] on main stream,
// [memset -> hist -> scan -> bucket] on side stream, join, aggregate.
// Streams/events created once (host resources, no device alloc).
// ---------------------------------------------------------------------------
extern "C" void kernel_launch(void* const* d_in, const int* in_sizes, int n_in,
                              void* d_out, int out_size)
{
    const float* h   = (const float*)d_in[0];
    const float* w   = (const float*)d_in[1];
    const float* ew  = (const float*)d_in[2];
    const int*   sv  = (const int*)d_in[3];
    const int*   dv  = (const int*)d_in[4];
    float* out       = (float*)d_out;

    const int M = in_sizes[0] / D;      // 100000
    const int E = in_sizes[2];          // 1600000

    static __half*   hp  = nullptr;
    static uint32_t* wt  = nullptr;
    static int*      cur = nullptr;
    static cudaStream_t s2 = nullptr;
    static cudaEvent_t ev_fork = nullptr, ev_join = nullptr;
    if (!hp)  cudaGetSymbolAddress((void**)&hp,  g_hp16);
    if (!wt)  cudaGetSymbolAddress((void**)&wt,  g_wt);
    if (!cur) cudaGetSymbolAddress((void**)&cur, g_cur);
    if (!s2) {
        cudaStreamCreateWithFlags(&s2, cudaStreamNonBlocking);
        cudaEventCreateWithFlags(&ev_fork, cudaEventDisableTiming);
        cudaEventCreateWithFlags(&ev_join, cudaEventDisableTiming);
    }

    // Fork: side stream branches off the capture (main) stream
    cudaEventRecord(ev_fork, 0);
    cudaStreamWaitEvent(s2, ev_fork, 0);

    // Branch A (main stream): W conversion -> GEMM
    convert_w_kernel<<<(D * D + 255) / 256, 256>>>(w);
    dim3 ggrid(D / 64, (M + 127) / 128);
    gemm_tf32_kernel<<<ggrid, 256>>>(h, wt, hp, M);

    // Branch B (side stream): CSR build
    cudaMemsetAsync(cur, 0, (size_t)M * sizeof(int), s2);
    int eblocks = min((E + 255) / 256, 148 * 8);
    hist_kernel<<<eblocks, 256, 0, s2>>>(dv, E);
    scan_kernel<<<1, 1024, 0, s2>>>(M);
    bucket_kernel<<<eblocks, 256, 0, s2>>>(sv, dv, ew, E);

    // Join: main stream waits for CSR branch
    cudaEventRecord(ev_join, s2);
    cudaStreamWaitEvent(0, ev_join, 0);

    // Aggregate (needs hp + CSR)
    aggregate_f16_kernel<<<(M + 1) / 2, 128>>>(hp, out, M);
}

// round 12
// speedup vs baseline: 1.5935x; 1.0043x over previous
#include <cuda_runtime.h>
#include <cuda_bf16.h>
#include <cuda_fp16.h>
#include <cstdint>

#define N_NODES 100000
#define N_EDGES_MAX 1600000
#define D 512

// Static device scratch
__device__ __half   g_hp16[(size_t)N_NODES * D];  // projected features fp16 (102.4 MB)
__device__ uint32_t g_wt[D * D];                  // W as tf32 bit patterns, [k][n] (1 MB)
__device__ int   g_cur[N_NODES];
__device__ int   g_off[N_NODES];
__device__ int2  g_edge[N_EDGES_MAX];

// ---------------------------------------------------------------------------
// tf32 helpers
// ---------------------------------------------------------------------------
__device__ __forceinline__ uint32_t to_tf32(float x)
{
    uint32_t r;
    asm("cvt.rna.tf32.f32 %0, %1;" : "=r"(r) : "f"(x));
    return r;
}

__device__ __forceinline__ void mma_tf32(float c[4], const uint32_t a[4], const uint32_t b[2])
{
    asm volatile(
        "mma.sync.aligned.m16n8k8.row.col.f32.tf32.tf32.f32 "
        "{%0,%1,%2,%3}, {%4,%5,%6,%7}, {%8,%9}, {%0,%1,%2,%3};"
        : "+f"(c[0]), "+f"(c[1]), "+f"(c[2]), "+f"(c[3])
        : "r"(a[0]), "r"(a[1]), "r"(a[2]), "r"(a[3]), "r"(b[0]), "r"(b[1]));
}

#define CP_ASYNC16(dst_smem_u32, src_ptr) \
    asm volatile("cp.async.cg.shared.global [%0], [%1], 16;" \
                 :: "r"(dst_smem_u32), "l"(src_ptr))
#define CP_ASYNC_COMMIT() asm volatile("cp.async.commit_group;")
#define CP_ASYNC_WAIT0()  asm volatile("cp.async.wait_group 0;")

// ---------------------------------------------------------------------------
// Kernel 0: W -> tf32 bit patterns
// ---------------------------------------------------------------------------
__global__ __launch_bounds__(256) void convert_w_kernel(const float* __restrict__ w)
{
    int i = blockIdx.x * blockDim.x + threadIdx.x;
    if (i < D * D) g_wt[i] = to_tf32(w[i]);
}

// ---------------------------------------------------------------------------
// Kernel 1: single-pass TF32 GEMM  hp16[M,512] = fp16(h @ W)
// BM=128, BN=128, BK=16. 8 warps, warp grid 4(m) x 2(n), warp tile 32x64
// = 2x8 m16n8k8 frags -> 32 mma per kt per warp (tensor-bound mix).
// ---------------------------------------------------------------------------
__global__ __launch_bounds__(256) void gemm_tf32_kernel(
    const float* __restrict__ h,
    const uint32_t* __restrict__ wt,
    __half* __restrict__ hp,
    int M)
{
    __shared__ float    As[2][128][20];    // stride 20: validated conflict-free
    __shared__ uint32_t Bs[2][16][136];    // stride 136: banks 8*tig+gid distinct

    const int tid  = threadIdx.x;
    const int wid  = tid >> 5;
    const int lane = tid & 31;
    const int gid  = lane >> 2;     // 0..7
    const int tig  = lane & 3;      // 0..3

    const int warp_m = wid & 3;     // 0..3 -> 32 rows each
    const int warp_n = wid >> 2;    // 0..1 -> 64 cols each

    const int m0 = blockIdx.x * 128;
    const int n0 = blockIdx.y * 128;

    // cp.async mappings
    const int arow = tid >> 2;          // 0..63
    const int acol = (tid & 3) * 4;     // 0,4,8,12
    const int gmA0 = min(m0 + arow,      M - 1);
    const int gmA1 = min(m0 + arow + 64, M - 1);
    const int brow = tid >> 5;          // 0..7 (two halves below)
    const int bchk = (tid & 31) * 4;    // 0..124 (u32 col, 16B chunks)

    auto load_tile = [&](int stage, int kt) {
        const int kbase = kt * 16;
        uint32_t d0 = (uint32_t)__cvta_generic_to_shared(&As[stage][arow][acol]);
        uint32_t d1 = (uint32_t)__cvta_generic_to_shared(&As[stage][arow + 64][acol]);
        CP_ASYNC16(d0, h + (size_t)gmA0 * D + kbase + acol);
        CP_ASYNC16(d1, h + (size_t)gmA1 * D + kbase + acol);
        uint32_t d2 = (uint32_t)__cvta_generic_to_shared(&Bs[stage][brow][bchk]);
        uint32_t d3 = (uint32_t)__cvta_generic_to_shared(&Bs[stage][brow + 8][bchk]);
        CP_ASYNC16(d2, wt + (size_t)(kbase + brow) * D + n0 + bchk);
        CP_ASYNC16(d3, wt + (size_t)(kbase + brow + 8) * D + n0 + bchk);
        CP_ASYNC_COMMIT();
    };

    float c[2][8][4];
    #pragma unroll
    for (int mi = 0; mi < 2; mi++)
        #pragma unroll
        for (int ni = 0; ni < 8; ni++)
            #pragma unroll
            for (int r = 0; r < 4; r++) c[mi][ni][r] = 0.0f;

    load_tile(0, 0);
    CP_ASYNC_WAIT0();
    __syncthreads();

    const int NK = D / 16;   // 32
    #pragma unroll 1
    for (int kt = 0; kt < NK; kt++) {
        const int s = kt & 1;
        if (kt + 1 < NK) load_tile(s ^ 1, kt + 1);

        #pragma unroll
        for (int ks = 0; ks < 2; ks++) {
            const int k0 = ks * 8;

            uint32_t a[2][4];
            #pragma unroll
            for (int mi = 0; mi < 2; mi++) {
                const int mb = warp_m * 32 + mi * 16;
                a[mi][0] = to_tf32(As[s][mb + gid    ][k0 + tig    ]);
                a[mi][1] = to_tf32(As[s][mb + gid + 8][k0 + tig    ]);
                a[mi][2] = to_tf32(As[s][mb + gid    ][k0 + tig + 4]);
                a[mi][3] = to_tf32(As[s][mb + gid + 8][k0 + tig + 4]);
            }
            uint32_t b[8][2];
            #pragma unroll
            for (int ni = 0; ni < 8; ni++) {
                const int cb = warp_n * 64 + ni * 8 + gid;
                b[ni][0] = Bs[s][k0 + tig    ][cb];
                b[ni][1] = Bs[s][k0 + tig + 4][cb];
            }

            #pragma unroll
            for (int mi = 0; mi < 2; mi++)
                #pragma unroll
                for (int ni = 0; ni < 8; ni++)
                    mma_tf32(c[mi][ni], a[mi], b[ni]);
        }

        CP_ASYNC_WAIT0();
        __syncthreads();
    }

    // Epilogue: fp16 stores
    #pragma unroll
    for (int mi = 0; mi < 2; mi++) {
        #pragma unroll
        for (int ni = 0; ni < 8; ni++) {
            const int mrow = m0 + warp_m * 32 + mi * 16 + gid;
            const int ncol = n0 + warp_n * 64 + ni * 8 + tig * 2;
            if (mrow < M) {
                __half2 v = __floats2half2_rn(c[mi][ni][0], c[mi][ni][1]);
                *reinterpret_cast<__half2*>(&hp[(size_t)mrow * D + ncol]) = v;
            }
            if (mrow + 8 < M) {
                __half2 v = __floats2half2_rn(c[mi][ni][2], c[mi][ni][3]);
                *reinterpret_cast<__half2*>(&hp[(size_t)(mrow + 8) * D + ncol]) = v;
            }
        }
    }
}

// ---------------------------------------------------------------------------
// CSR build kernels
// ---------------------------------------------------------------------------
__global__ __launch_bounds__(256) void hist_kernel(const int* __restrict__ dst, int E)
{
    int i = blockIdx.x * blockDim.x + threadIdx.x;
    int stride = gridDim.x * blockDim.x;
    for (; i < E; i += stride)
        atomicAdd(&g_cur[dst[i]], 1);
}

__global__ __launch_bounds__(1024) void scan_kernel(int N)
{
    __shared__ int part[1024];
    const int t = threadIdx.x;
    const int chunk = (N + 1023) / 1024;
    const int begin = min(t * chunk, N);
    const int end   = min(begin + chunk, N);

    int sum = 0;
    for (int i = begin; i < end; i++) sum += g_cur[i];
    part[t] = sum;
    __syncthreads();

    #pragma unroll
    for (int s = 1; s < 1024; s <<= 1) {
        int v = (t >= s) ? part[t - s] : 0;
        __syncthreads();
        part[t] += v;
        __syncthreads();
    }

    int off = (t == 0) ? 0 : part[t - 1];
    for (int i = begin; i < end; i++) {
        int d = g_cur[i];
        g_off[i] = off;
        g_cur[i] = off;
        off += d;
    }
}

__global__ __launch_bounds__(256) void bucket_kernel(
    const int* __restrict__ src,
    const int* __restrict__ dst,
    const float* __restrict__ ew,
    int E)
{
    int i = blockIdx.x * blockDim.x + threadIdx.x;
    int stride = gridDim.x * blockDim.x;
    for (; i < E; i += stride) {
        int d = dst[i];
        int p = atomicAdd(&g_cur[d], 1);
        g_edge[p] = make_int2(src[i], __float_as_int(ew[i]));
    }
}

// ---------------------------------------------------------------------------
// Kernel 4: per-node fp16 gather-aggregate + fused ReLU.
// ---------------------------------------------------------------------------
__global__ __launch_bounds__(128) void aggregate_f16_kernel(
    const __half* __restrict__ hp,
    float* __restrict__ out,
    int N)
{
    const int sub = threadIdx.x >> 6;
    const int tt  = threadIdx.x & 63;
    const int n = blockIdx.x * 2 + sub;
    if (n >= N) return;
    const int col = tt * 8;

    int j  = g_off[n];
    const int je = g_cur[n];

    float a0[8] = {0.f,0.f,0.f,0.f,0.f,0.f,0.f,0.f};
    float a1[8] = {0.f,0.f,0.f,0.f,0.f,0.f,0.f,0.f};

    for (; j + 1 < je; j += 2) {
        int2 e0 = __ldg(&g_edge[j]);
        int2 e1 = __ldg(&g_edge[j + 1]);
        float w0 = __int_as_float(e0.y);
        float w1 = __int_as_float(e1.y);
        uint4 p0 = *reinterpret_cast<const uint4*>(hp + (size_t)e0.x * D + col);
        uint4 p1 = *reinterpret_cast<const uint4*>(hp + (size_t)e1.x * D + col);

        float2 f;
        f = __half22float2(*reinterpret_cast<__half2*>(&p0.x)); a0[0] += w0*f.x; a0[1] += w0*f.y;
        f = __half22float2(*reinterpret_cast<__half2*>(&p0.y)); a0[2] += w0*f.x; a0[3] += w0*f.y;
        f = __half22float2(*reinterpret_cast<__half2*>(&p0.z)); a0[4] += w0*f.x; a0[5] += w0*f.y;
        f = __half22float2(*reinterpret_cast<__half2*>(&p0.w)); a0[6] += w0*f.x; a0[7] += w0*f.y;
        f = __half22float2(*reinterpret_cast<__half2*>(&p1.x)); a1[0] += w1*f.x; a1[1] += w1*f.y;
        f = __half22float2(*reinterpret_cast<__half2*>(&p1.y)); a1[2] += w1*f.x; a1[3] += w1*f.y;
        f = __half22float2(*reinterpret_cast<__half2*>(&p1.z)); a1[4] += w1*f.x; a1[5] += w1*f.y;
        f = __half22float2(*reinterpret_cast<__half2*>(&p1.w)); a1[6] += w1*f.x; a1[7] += w1*f.y;
    }
    if (j < je) {
        int2 e0 = __ldg(&g_edge[j]);
        float w0 = __int_as_float(e0.y);
        uint4 p0 = *reinterpret_cast<const uint4*>(hp + (size_t)e0.x * D + col);
        float2 f;
        f = __half22float2(*reinterpret_cast<__half2*>(&p0.x)); a0[0] += w0*f.x; a0[1] += w0*f.y;
        f = __half22float2(*reinterpret_cast<__half2*>(&p0.y)); a0[2] += w0*f.x; a0[3] += w0*f.y;
        f = __half22float2(*reinterpret_cast<__half2*>(&p0.z)); a0[4] += w0*f.x; a0[5] += w0*f.y;
        f = __half22float2(*reinterpret_cast<__half2*>(&p0.w)); a0[6] += w0*f.x; a0[7] += w0*f.y;
    }

    float4 r0, r1;
    r0.x = fmaxf(a0[0] + a1[0], 0.f);
    r0.y = fmaxf(a0[1] + a1[1], 0.f);
    r0.z = fmaxf(a0[2] + a1[2], 0.f);
    r0.w = fmaxf(a0[3] + a1[3], 0.f);
    r1.x = fmaxf(a0[4] + a1[4], 0.f);
    r1.y = fmaxf(a0[5] + a1[5], 0.f);
    r1.z = fmaxf(a0[6] + a1[6], 0.f);
    r1.w = fmaxf(a0[7] + a1[7], 0.f);
    *reinterpret_cast<float4*>(out + (size_t)n * D + col)     = r0;
    *reinterpret_cast<float4*>(out + (size_t)n * D + col + 4) = r1;
}

// ---------------------------------------------------------------------------
// Launch — graph-parallel fork/join (validated round 11)
// ---------------------------------------------------------------------------
extern "C" void kernel_launch(void* const* d_in, const int* in_sizes, int n_in,
                              void* d_out, int out_size)
{
    const float* h   = (const float*)d_in[0];
    const float* w   = (const float*)d_in[1];
    const float* ew  = (const float*)d_in[2];
    const int*   sv  = (const int*)d_in[3];
    const int*   dv  = (const int*)d_in[4];
    float* out       = (float*)d_out;

    const int M = in_sizes[0] / D;      // 100000
    const int E = in_sizes[2];          // 1600000

    static __half*   hp  = nullptr;
    static uint32_t* wt  = nullptr;
    static int*      cur = nullptr;
    static cudaStream_t s2 = nullptr;
    static cudaEvent_t ev_fork = nullptr, ev_join = nullptr;
    if (!hp)  cudaGetSymbolAddress((void**)&hp,  g_hp16);
    if (!wt)  cudaGetSymbolAddress((void**)&wt,  g_wt);
    if (!cur) cudaGetSymbolAddress((void**)&cur, g_cur);
    if (!s2) {
        cudaStreamCreateWithFlags(&s2, cudaStreamNonBlocking);
        cudaEventCreateWithFlags(&ev_fork, cudaEventDisableTiming);
        cudaEventCreateWithFlags(&ev_join, cudaEventDisableTiming);
    }

    // Fork
    cudaEventRecord(ev_fork, 0);
    cudaStreamWaitEvent(s2, ev_fork, 0);

    // Branch A (main): W conversion -> GEMM
    convert_w_kernel<<<(D * D + 255) / 256, 256>>>(w);
    dim3 ggrid((M + 127) / 128, D / 128);
    gemm_tf32_kernel<<<ggrid, 256>>>(h, wt, hp, M);

    // Branch B (side): CSR build
    cudaMemsetAsync(cur, 0, (size_t)M * sizeof(int), s2);
    int eblocks = min((E + 255) / 256, 148 * 8);
    hist_kernel<<<eblocks, 256, 0, s2>>>(dv, E);
    scan_kernel<<<1, 1024, 0, s2>>>(M);
    bucket_kernel<<<eblocks, 256, 0, s2>>>(sv, dv, ew, E);

    // Join
    cudaEventRecord(ev_join, s2);
    cudaStreamWaitEvent(0, ev_join, 0);

    // Aggregate
    aggregate_f16_kernel<<<(M + 1) / 2, 128>>>(hp, out, M);
}

// round 13
// speedup vs baseline: 1.9289x; 1.2105x over previous
#include <cuda_runtime.h>
#include <cuda_bf16.h>
#include <cuda_fp16.h>
#include <cstdint>

#define N_NODES 100000
#define N_EDGES_MAX 1600000
#define D 512

// Static device scratch
__device__ __half   g_hp16[(size_t)N_NODES * D];  // projected features fp16 (102.4 MB)
__device__ uint32_t g_wt[D * D];                  // W as tf32 bit patterns, [k][n] (1 MB)
__device__ int   g_cur[N_NODES];
__device__ int   g_off[N_NODES];
__device__ int2  g_edge[N_EDGES_MAX];

// ---------------------------------------------------------------------------
// tf32 helpers
// ---------------------------------------------------------------------------
__device__ __forceinline__ uint32_t to_tf32(float x)
{
    uint32_t r;
    asm("cvt.rna.tf32.f32 %0, %1;" : "=r"(r) : "f"(x));
    return r;
}

__device__ __forceinline__ void mma_tf32(float c[4], const uint32_t a[4], const uint32_t b[2])
{
    asm volatile(
        "mma.sync.aligned.m16n8k8.row.col.f32.tf32.tf32.f32 "
        "{%0,%1,%2,%3}, {%4,%5,%6,%7}, {%8,%9}, {%0,%1,%2,%3};"
        : "+f"(c[0]), "+f"(c[1]), "+f"(c[2]), "+f"(c[3])
        : "r"(a[0]), "r"(a[1]), "r"(a[2]), "r"(a[3]), "r"(b[0]), "r"(b[1]));
}

#define CP_ASYNC16(dst_smem_u32, src_ptr) \
    asm volatile("cp.async.cg.shared.global [%0], [%1], 16;" \
                 :: "r"(dst_smem_u32), "l"(src_ptr))
#define CP_ASYNC_COMMIT() asm volatile("cp.async.commit_group;")
#define CP_ASYNC_WAIT0()  asm volatile("cp.async.wait_group 0;" ::: "memory")
#define CP_ASYNC_WAIT1()  asm volatile("cp.async.wait_group 1;" ::: "memory")

// GEMM smem geometry (dynamic): 3 stages of As[128][20] f32 + Bs[16][136] u32
#define AS_STRIDE 20
#define BS_STRIDE 136
#define AS_STAGE  (128 * AS_STRIDE)          // floats
#define BS_STAGE  (16 * BS_STRIDE)           // u32
#define SMEM_GEMM_BYTES (3 * (AS_STAGE + BS_STAGE) * 4)   // 56832

// ---------------------------------------------------------------------------
// Kernel 0: W -> tf32 bit patterns
// ---------------------------------------------------------------------------
__global__ __launch_bounds__(256) void convert_w_kernel(const float* __restrict__ w)
{
    int i = blockIdx.x * blockDim.x + threadIdx.x;
    if (i < D * D) g_wt[i] = to_tf32(w[i]);
}

// ---------------------------------------------------------------------------
// Kernel 1: single-pass TF32 GEMM  hp16[M,512] = fp16(h @ W)
// BM=128, BN=128, BK=16; warp tile 32x64 (2x8 m16n8k8).
// 3-stage cp.async pipeline (wait_group 1); 2 CTAs/SM forced.
// ---------------------------------------------------------------------------
__global__ __launch_bounds__(256, 2) void gemm_tf32_kernel(
    const float* __restrict__ h,
    const uint32_t* __restrict__ wt,
    __half* __restrict__ hp,
    int M)
{
    extern __shared__ char smem_raw[];
    float*    Asm = reinterpret_cast<float*>(smem_raw);
    uint32_t* Bsm = reinterpret_cast<uint32_t*>(smem_raw + 3 * AS_STAGE * 4);

    const int tid  = threadIdx.x;
    const int wid  = tid >> 5;
    const int lane = tid & 31;
    const int gid  = lane >> 2;     // 0..7
    const int tig  = lane & 3;      // 0..3

    const int warp_m = wid & 3;     // 32 rows each
    const int warp_n = wid >> 2;    // 64 cols each

    const int m0 = blockIdx.x * 128;
    const int n0 = blockIdx.y * 128;

    const int arow = tid >> 2;          // 0..63
    const int acol = (tid & 3) * 4;     // 0,4,8,12
    const int gmA0 = min(m0 + arow,      M - 1);
    const int gmA1 = min(m0 + arow + 64, M - 1);
    const int brow = tid >> 5;          // 0..7
    const int bchk = (tid & 31) * 4;    // 0..124

    auto load_tile = [&](int stage, int kt) {
        const int kbase = kt * 16;
        float*    As = Asm + stage * AS_STAGE;
        uint32_t* Bs = Bsm + stage * BS_STAGE;
        uint32_t d0 = (uint32_t)__cvta_generic_to_shared(&As[arow * AS_STRIDE + acol]);
        uint32_t d1 = (uint32_t)__cvta_generic_to_shared(&As[(arow + 64) * AS_STRIDE + acol]);
        CP_ASYNC16(d0, h + (size_t)gmA0 * D + kbase + acol);
        CP_ASYNC16(d1, h + (size_t)gmA1 * D + kbase + acol);
        uint32_t d2 = (uint32_t)__cvta_generic_to_shared(&Bs[brow * BS_STRIDE + bchk]);
        uint32_t d3 = (uint32_t)__cvta_generic_to_shared(&Bs[(brow + 8) * BS_STRIDE + bchk]);
        CP_ASYNC16(d2, wt + (size_t)(kbase + brow) * D + n0 + bchk);
        CP_ASYNC16(d3, wt + (size_t)(kbase + brow + 8) * D + n0 + bchk);
        CP_ASYNC_COMMIT();
    };

    float c[2][8][4];
    #pragma unroll
    for (int mi = 0; mi < 2; mi++)
        #pragma unroll
        for (int ni = 0; ni < 8; ni++)
            #pragma unroll
            for (int r = 0; r < 4; r++) c[mi][ni][r] = 0.0f;

    const int NK = D / 16;   // 32
    load_tile(0, 0);
    load_tile(1, 1);

    #pragma unroll 1
    for (int kt = 0; kt < NK; kt++) {
        const int s = kt % 3;
        if (kt == NK - 1) { CP_ASYNC_WAIT0(); } else { CP_ASYNC_WAIT1(); }
        __syncthreads();
        if (kt + 2 < NK) load_tile((kt + 2) % 3, kt + 2);

        const float*    As = Asm + s * AS_STAGE;
        const uint32_t* Bs = Bsm + s * BS_STAGE;

        #pragma unroll
        for (int ks = 0; ks < 2; ks++) {
            const int k0 = ks * 8;

            uint32_t a[2][4];
            #pragma unroll
            for (int mi = 0; mi < 2; mi++) {
                const int mb = warp_m * 32 + mi * 16;
                a[mi][0] = to_tf32(As[(mb + gid    ) * AS_STRIDE + k0 + tig    ]);
                a[mi][1] = to_tf32(As[(mb + gid + 8) * AS_STRIDE + k0 + tig    ]);
                a[mi][2] = to_tf32(As[(mb + gid    ) * AS_STRIDE + k0 + tig + 4]);
                a[mi][3] = to_tf32(As[(mb + gid + 8) * AS_STRIDE + k0 + tig + 4]);
            }
            uint32_t b[8][2];
            #pragma unroll
            for (int ni = 0; ni < 8; ni++) {
                const int cb = warp_n * 64 + ni * 8 + gid;
                b[ni][0] = Bs[(k0 + tig    ) * BS_STRIDE + cb];
                b[ni][1] = Bs[(k0 + tig + 4) * BS_STRIDE + cb];
            }

            #pragma unroll
            for (int mi = 0; mi < 2; mi++)
                #pragma unroll
                for (int ni = 0; ni < 8; ni++)
                    mma_tf32(c[mi][ni], a[mi], b[ni]);
        }
        __syncthreads();
    }

    // Epilogue: fp16 stores
    #pragma unroll
    for (int mi = 0; mi < 2; mi++) {
        #pragma unroll
        for (int ni = 0; ni < 8; ni++) {
            const int mrow = m0 + warp_m * 32 + mi * 16 + gid;
            const int ncol = n0 + warp_n * 64 + ni * 8 + tig * 2;
            if (mrow < M) {
                __half2 v = __floats2half2_rn(c[mi][ni][0], c[mi][ni][1]);
                *reinterpret_cast<__half2*>(&g_hp16[(size_t)mrow * D + ncol]) = v;
            }
            if (mrow + 8 < M) {
                __half2 v = __floats2half2_rn(c[mi][ni][2], c[mi][ni][3]);
                *reinterpret_cast<__half2*>(&g_hp16[(size_t)(mrow + 8) * D + ncol]) = v;
            }
        }
    }
    (void)hp;
}

// ---------------------------------------------------------------------------
// CSR build kernels
// ---------------------------------------------------------------------------
__global__ __launch_bounds__(256) void hist_kernel(const int* __restrict__ dst, int E)
{
    int i = blockIdx.x * blockDim.x + threadIdx.x;
    int stride = gridDim.x * blockDim.x;
    for (; i < E; i += stride)
        atomicAdd(&g_cur[dst[i]], 1);
}

// Single-block tiled scan: coalesced loads, shuffle warp-scan per 1024-tile.
__global__ __launch_bounds__(1024) void scan_kernel(int N)
{
    __shared__ int wsum[32];
    __shared__ int carry_s;
    const int t = threadIdx.x, lane = t & 31, wrp = t >> 5;
    if (t == 0) carry_s = 0;
    __syncthreads();

    for (int base = 0; base < N; base += 1024) {
        int i = base + t;
        int v = (i < N) ? g_cur[i] : 0;

        // warp inclusive scan
        int x = v;
        #pragma unroll
        for (int s = 1; s < 32; s <<= 1) {
            int u = __shfl_up_sync(0xFFFFFFFFu, x, s);
            if (lane >= s) x += u;
        }
        if (lane == 31) wsum[wrp] = x;
        __syncthreads();

        // warp 0 scans the 32 warp totals
        if (wrp == 0) {
            int y = wsum[lane];
            #pragma unroll
            for (int s = 1; s < 32; s <<= 1) {
                int u = __shfl_up_sync(0xFFFFFFFFu, y, s);
                if (lane >= s) y += u;
            }
            wsum[lane] = y;
        }
        __syncthreads();

        int warp_excl = (wrp == 0) ? 0 : wsum[wrp - 1];
        int excl = x - v + warp_excl + carry_s;
        if (i < N) { g_off[i] = excl; g_cur[i] = excl; }
        int total = wsum[31];
        __syncthreads();
        if (t == 0) carry_s += total;
        __syncthreads();
    }
}

__global__ __launch_bounds__(256) void bucket_kernel(
    const int* __restrict__ src,
    const int* __restrict__ dst,
    const float* __restrict__ ew,
    int E)
{
    int i = blockIdx.x * blockDim.x + threadIdx.x;
    int stride = gridDim.x * blockDim.x;
    for (; i < E; i += stride) {
        int d = dst[i];
        int p = atomicAdd(&g_cur[d], 1);
        g_edge[p] = make_int2(src[i], __float_as_int(ew[i]));
    }
}

// ---------------------------------------------------------------------------
// Kernel 4: per-node fp16 gather-aggregate + fused ReLU.
// ---------------------------------------------------------------------------
__global__ __launch_bounds__(128) void aggregate_f16_kernel(
    const __half* __restrict__ hp,
    float* __restrict__ out,
    int N)
{
    const int sub = threadIdx.x >> 6;
    const int tt  = threadIdx.x & 63;
    const int n = blockIdx.x * 2 + sub;
    if (n >= N) return;
    const int col = tt * 8;

    int j  = g_off[n];
    const int je = g_cur[n];

    float a0[8] = {0.f,0.f,0.f,0.f,0.f,0.f,0.f,0.f};
    float a1[8] = {0.f,0.f,0.f,0.f,0.f,0.f,0.f,0.f};

    for (; j + 1 < je; j += 2) {
        int2 e0 = __ldg(&g_edge[j]);
        int2 e1 = __ldg(&g_edge[j + 1]);
        float w0 = __int_as_float(e0.y);
        float w1 = __int_as_float(e1.y);
        uint4 p0 = *reinterpret_cast<const uint4*>(hp + (size_t)e0.x * D + col);
        uint4 p1 = *reinterpret_cast<const uint4*>(hp + (size_t)e1.x * D + col);

        float2 f;
        f = __half22float2(*reinterpret_cast<__half2*>(&p0.x)); a0[0] += w0*f.x; a0[1] += w0*f.y;
        f = __half22float2(*reinterpret_cast<__half2*>(&p0.y)); a0[2] += w0*f.x; a0[3] += w0*f.y;
        f = __half22float2(*reinterpret_cast<__half2*>(&p0.z)); a0[4] += w0*f.x; a0[5] += w0*f.y;
        f = __half22float2(*reinterpret_cast<__half2*>(&p0.w)); a0[6] += w0*f.x; a0[7] += w0*f.y;
        f = __half22float2(*reinterpret_cast<__half2*>(&p1.x)); a1[0] += w1*f.x; a1[1] += w1*f.y;
        f = __half22float2(*reinterpret_cast<__half2*>(&p1.y)); a1[2] += w1*f.x; a1[3] += w1*f.y;
        f = __half22float2(*reinterpret_cast<__half2*>(&p1.z)); a1[4] += w1*f.x; a1[5] += w1*f.y;
        f = __half22float2(*reinterpret_cast<__half2*>(&p1.w)); a1[6] += w1*f.x; a1[7] += w1*f.y;
    }
    if (j < je) {
        int2 e0 = __ldg(&g_edge[j]);
        float w0 = __int_as_float(e0.y);
        uint4 p0 = *reinterpret_cast<const uint4*>(hp + (size_t)e0.x * D + col);
        float2 f;
        f = __half22float2(*reinterpret_cast<__half2*>(&p0.x)); a0[0] += w0*f.x; a0[1] += w0*f.y;
        f = __half22float2(*reinterpret_cast<__half2*>(&p0.y)); a0[2] += w0*f.x; a0[3] += w0*f.y;
        f = __half22float2(*reinterpret_cast<__half2*>(&p0.z)); a0[4] += w0*f.x; a0[5] += w0*f.y;
        f = __half22float2(*reinterpret_cast<__half2*>(&p0.w)); a0[6] += w0*f.x; a0[7] += w0*f.y;
    }

    float4 r0, r1;
    r0.x = fmaxf(a0[0] + a1[0], 0.f);
    r0.y = fmaxf(a0[1] + a1[1], 0.f);
    r0.z = fmaxf(a0[2] + a1[2], 0.f);
    r0.w = fmaxf(a0[3] + a1[3], 0.f);
    r1.x = fmaxf(a0[4] + a1[4], 0.f);
    r1.y = fmaxf(a0[5] + a1[5], 0.f);
    r1.z = fmaxf(a0[6] + a1[6], 0.f);
    r1.w = fmaxf(a0[7] + a1[7], 0.f);
    *reinterpret_cast<float4*>(out + (size_t)n * D + col)     = r0;
    *reinterpret_cast<float4*>(out + (size_t)n * D + col + 4) = r1;
}

// ---------------------------------------------------------------------------
// Launch — graph-parallel fork/join
// ---------------------------------------------------------------------------
extern "C" void kernel_launch(void* const* d_in, const int* in_sizes, int n_in,
                              void* d_out, int out_size)
{
    const float* h   = (const float*)d_in[0];
    const float* w   = (const float*)d_in[1];
    const float* ew  = (const float*)d_in[2];
    const int*   sv  = (const int*)d_in[3];
    const int*   dv  = (const int*)d_in[4];
    float* out       = (float*)d_out;

    const int M = in_sizes[0] / D;      // 100000
    const int E = in_sizes[2];          // 1600000

    static __half*   hp  = nullptr;
    static uint32_t* wt  = nullptr;
    static int*      cur = nullptr;
    static cudaStream_t s2 = nullptr;
    static cudaEvent_t ev_fork = nullptr, ev_join = nullptr;
    static bool attr_set = false;
    if (!hp)  cudaGetSymbolAddress((void**)&hp,  g_hp16);
    if (!wt)  cudaGetSymbolAddress((void**)&wt,  g_wt);
    if (!cur) cudaGetSymbolAddress((void**)&cur, g_cur);
    if (!s2) {
        cudaStreamCreateWithFlags(&s2, cudaStreamNonBlocking);
        cudaEventCreateWithFlags(&ev_fork, cudaEventDisableTiming);
        cudaEventCreateWithFlags(&ev_join, cudaEventDisableTiming);
    }
    if (!attr_set) {
        cudaFuncSetAttribute(gemm_tf32_kernel,
                             cudaFuncAttributeMaxDynamicSharedMemorySize, SMEM_GEMM_BYTES);
        attr_set = true;
    }

    // Fork
    cudaEventRecord(ev_fork, 0);
    cudaStreamWaitEvent(s2, ev_fork, 0);

    // Branch A (main): W conversion -> GEMM
    convert_w_kernel<<<(D * D + 255) / 256, 256>>>(w);
    dim3 ggrid((M + 127) / 128, D / 128);
    gemm_tf32_kernel<<<ggrid, 256, SMEM_GEMM_BYTES>>>(h, wt, hp, M);

    // Branch B (side): CSR build
    cudaMemsetAsync(cur, 0, (size_t)M * sizeof(int), s2);
    int eblocks = min((E + 255) / 256, 148 * 8);
    hist_kernel<<<eblocks, 256, 0, s2>>>(dv, E);
    scan_kernel<<<1, 1024, 0, s2>>>(M);
    bucket_kernel<<<eblocks, 256, 0, s2>>>(sv, dv, ew, E);

    // Join
    cudaEventRecord(ev_join, s2);
    cudaStreamWaitEvent(0, ev_join, 0);

    // Aggregate
    aggregate_f16_kernel<<<(M + 1) / 2, 128>>>(hp, out, M);
}

// round 14
// speedup vs baseline: 2.5060x; 1.2992x over previous
#include <cuda_runtime.h>
#include <cuda_bf16.h>
#include <cuda_fp16.h>
#include <cstdint>

#define N_NODES 100000
#define N_EDGES_MAX 1600000
#define D 512

// Static device scratch
__device__ __half g_hp16[(size_t)N_NODES * D];  // projected features fp16 (102.4 MB)
__device__ __half g_wf16[D * D];                // W fp16, transposed [n][k] (0.5 MB)
__device__ int   g_cur[N_NODES];
__device__ int   g_off[N_NODES];
__device__ int2  g_edge[N_EDGES_MAX];

// ---------------------------------------------------------------------------
// fp16 mma m16n8k16 (fp32 accumulate)
// ---------------------------------------------------------------------------
__device__ __forceinline__ void mma_f16(float c[4], const uint32_t a[4], const uint32_t b[2])
{
    asm volatile(
        "mma.sync.aligned.m16n8k16.row.col.f32.f16.f16.f32 "
        "{%0,%1,%2,%3}, {%4,%5,%6,%7}, {%8,%9}, {%0,%1,%2,%3};"
        : "+f"(c[0]), "+f"(c[1]), "+f"(c[2]), "+f"(c[3])
        : "r"(a[0]), "r"(a[1]), "r"(a[2]), "r"(a[3]), "r"(b[0]), "r"(b[1]));
}

__device__ __forceinline__ uint32_t pack_h2(float x, float y)
{
    __half2 h = __floats2half2_rn(x, y);
    return reinterpret_cast<uint32_t&>(h);
}

#define CP_ASYNC16(dst_smem_u32, src_ptr) \
    asm volatile("cp.async.cg.shared.global [%0], [%1], 16;" \
                 :: "r"(dst_smem_u32), "l"(src_ptr))
#define CP_ASYNC_COMMIT() asm volatile("cp.async.commit_group;")
#define CP_ASYNC_WAIT0()  asm volatile("cp.async.wait_group 0;" ::: "memory")
#define CP_ASYNC_WAIT1()  asm volatile("cp.async.wait_group 1;" ::: "memory")

// GEMM smem: 3 stages. As[128][40] f32 (stride 40: banks 8*gid, conflict-free
// per LDS.64 half-warp phase). Bs[128 n][20 u32] fp16 (stride 20: validated
// distinct-octet pattern 20*gid+tig).
#define AS_STRIDE 40
#define BS_STRIDE 20
#define AS_STAGE  (128 * AS_STRIDE)          // floats
#define BS_STAGE  (128 * BS_STRIDE)          // u32
#define SMEM_GEMM_BYTES (3 * (AS_STAGE + BS_STAGE) * 4)   // 92160

// ---------------------------------------------------------------------------
// Kernel 0: W -> fp16, transposed [n][k]
// ---------------------------------------------------------------------------
__global__ __launch_bounds__(256) void convert_w_kernel(const float* __restrict__ w)
{
    int i = blockIdx.x * blockDim.x + threadIdx.x;   // i = n*512 + k
    if (i >= D * D) return;
    int n = i >> 9;
    int k = i & 511;
    g_wf16[i] = __float2half_rn(w[(size_t)k * D + n]);
}

// ---------------------------------------------------------------------------
// Kernel 1: single-pass FP16 GEMM  hp16[M,512] = fp16(h @ W)
// BM=128, BN=128, BK=32; warp tile 32x64 (2x8 m16n8k16 frags).
// 3-stage cp.async pipeline; 2 CTAs/SM.
// ---------------------------------------------------------------------------
__global__ __launch_bounds__(256, 2) void gemm_f16_kernel(
    const float* __restrict__ h,
    const __half* __restrict__ wf,    // [n][k]
    int M)
{
    extern __shared__ char smem_raw[];
    float*    Asm = reinterpret_cast<float*>(smem_raw);
    uint32_t* Bsm = reinterpret_cast<uint32_t*>(smem_raw + 3 * AS_STAGE * 4);

    const int tid  = threadIdx.x;
    const int wid  = tid >> 5;
    const int lane = tid & 31;
    const int gid  = lane >> 2;     // 0..7
    const int tig  = lane & 3;      // 0..3

    const int warp_m = wid & 3;     // 32 rows each
    const int warp_n = wid >> 2;    // 64 cols each

    const int m0 = blockIdx.x * 128;
    const int n0 = blockIdx.y * 128;

    auto load_tile = [&](int stage, int kt) {
        const int kbase = kt * 32;
        float*    As = Asm + stage * AS_STAGE;
        uint32_t* Bs = Bsm + stage * BS_STAGE;
        // A: 128 rows x 32 k fp32 = 16KB -> 1024 chunks, 4/thread
        #pragma unroll
        for (int l = 0; l < 4; l++) {
            int e = tid + l * 256;
            int row = e >> 3, chunk = e & 7;
            int gm = min(m0 + row, M - 1);
            uint32_t d = (uint32_t)__cvta_generic_to_shared(&As[row * AS_STRIDE + chunk * 4]);
            CP_ASYNC16(d, h + (size_t)gm * D + kbase + chunk * 4);
        }
        // B: 128 n-rows x 32 k fp16 = 8KB -> 512 chunks, 2/thread
        #pragma unroll
        for (int l = 0; l < 2; l++) {
            int e = tid + l * 256;
            int row = e >> 2, chunk = e & 3;
            uint32_t d = (uint32_t)__cvta_generic_to_shared(&Bs[row * BS_STRIDE + chunk * 4]);
            CP_ASYNC16(d, wf + (size_t)(n0 + row) * D + kbase + chunk * 8);
        }
        CP_ASYNC_COMMIT();
    };

    float c[2][8][4];
    #pragma unroll
    for (int mi = 0; mi < 2; mi++)
        #pragma unroll
        for (int ni = 0; ni < 8; ni++)
            #pragma unroll
            for (int r = 0; r < 4; r++) c[mi][ni][r] = 0.0f;

    const int NK = D / 32;   // 16
    load_tile(0, 0);
    load_tile(1, 1);

    #pragma unroll 1
    for (int kt = 0; kt < NK; kt++) {
        const int s = kt % 3;
        if (kt == NK - 1) { CP_ASYNC_WAIT0(); } else { CP_ASYNC_WAIT1(); }
        __syncthreads();
        if (kt + 2 < NK) load_tile((kt + 2) % 3, kt + 2);

        const float*    As = Asm + s * AS_STAGE;
        const uint32_t* Bs = Bsm + s * BS_STAGE;

        #pragma unroll
        for (int ks = 0; ks < 2; ks++) {
            const int kf = ks * 16;    // fp16-k offset (A floats / B: 8 u32)

            // A fragments: pack fp32 pairs -> fp16x2 (validated k16 mapping)
            uint32_t a[2][4];
            #pragma unroll
            for (int mi = 0; mi < 2; mi++) {
                const int mb = warp_m * 32 + mi * 16;
                float2 f0 = *reinterpret_cast<const float2*>(&As[(mb + gid    ) * AS_STRIDE + kf + 2 * tig    ]);
                float2 f1 = *reinterpret_cast<const float2*>(&As[(mb + gid + 8) * AS_STRIDE + kf + 2 * tig    ]);
                float2 f2 = *reinterpret_cast<const float2*>(&As[(mb + gid    ) * AS_STRIDE + kf + 2 * tig + 8]);
                float2 f3 = *reinterpret_cast<const float2*>(&As[(mb + gid + 8) * AS_STRIDE + kf + 2 * tig + 8]);
                a[mi][0] = pack_h2(f0.x, f0.y);
                a[mi][1] = pack_h2(f1.x, f1.y);
                a[mi][2] = pack_h2(f2.x, f2.y);
                a[mi][3] = pack_h2(f3.x, f3.y);
            }
            // B fragments: direct u32 from [n][k] fp16 smem
            uint32_t b[8][2];
            #pragma unroll
            for (int ni = 0; ni < 8; ni++) {
                const int cb = warp_n * 64 + ni * 8 + gid;
                b[ni][0] = Bs[cb * BS_STRIDE + 8 * ks + tig    ];
                b[ni][1] = Bs[cb * BS_STRIDE + 8 * ks + tig + 4];
            }

            #pragma unroll
            for (int mi = 0; mi < 2; mi++)
                #pragma unroll
                for (int ni = 0; ni < 8; ni++)
                    mma_f16(c[mi][ni], a[mi], b[ni]);
        }
        __syncthreads();
    }

    // Epilogue: fp16 stores
    #pragma unroll
    for (int mi = 0; mi < 2; mi++) {
        #pragma unroll
        for (int ni = 0; ni < 8; ni++) {
            const int mrow = m0 + warp_m * 32 + mi * 16 + gid;
            const int ncol = n0 + warp_n * 64 + ni * 8 + tig * 2;
            if (mrow < M) {
                __half2 v = __floats2half2_rn(c[mi][ni][0], c[mi][ni][1]);
                *reinterpret_cast<__half2*>(&g_hp16[(size_t)mrow * D + ncol]) = v;
            }
            if (mrow + 8 < M) {
                __half2 v = __floats2half2_rn(c[mi][ni][2], c[mi][ni][3]);
                *reinterpret_cast<__half2*>(&g_hp16[(size_t)(mrow + 8) * D + ncol]) = v;
            }
        }
    }
}

// ---------------------------------------------------------------------------
// CSR build kernels
// ---------------------------------------------------------------------------
__global__ __launch_bounds__(256) void hist_kernel(const int* __restrict__ dst, int E)
{
    int i = blockIdx.x * blockDim.x + threadIdx.x;
    int stride = gridDim.x * blockDim.x;
    for (; i < E; i += stride)
        atomicAdd(&g_cur[dst[i]], 1);
}

// Single-block scan, int4 per thread per tile (4096 elems/tile).
// N assumed divisible by 4 (N = 100000).
__global__ __launch_bounds__(1024) void scan_kernel(int N)
{
    __shared__ int wsum[32];
    __shared__ int carry_s;
    const int t = threadIdx.x, lane = t & 31, wrp = t >> 5;
    if (t == 0) carry_s = 0;
    __syncthreads();

    const int N4 = N >> 2;
    for (int base = 0; base < N4; base += 1024) {
        int i = base + t;
        int4 v = (i < N4) ? reinterpret_cast<const int4*>(g_cur)[i]
                          : make_int4(0, 0, 0, 0);
        int s = v.x + v.y + v.z + v.w;

        int x = s;
        #pragma unroll
        for (int sh = 1; sh < 32; sh <<= 1) {
            int u = __shfl_up_sync(0xFFFFFFFFu, x, sh);
            if (lane >= sh) x += u;
        }
        if (lane == 31) wsum[wrp] = x;
        __syncthreads();

        if (wrp == 0) {
            int y = wsum[lane];
            #pragma unroll
            for (int sh = 1; sh < 32; sh <<= 1) {
                int u = __shfl_up_sync(0xFFFFFFFFu, y, sh);
                if (lane >= sh) y += u;
            }
            wsum[lane] = y;
        }
        __syncthreads();

        int excl = x - s + ((wrp == 0) ? 0 : wsum[wrp - 1]) + carry_s;
        if (i < N4) {
            int4 o;
            o.x = excl;
            o.y = o.x + v.x;
            o.z = o.y + v.y;
            o.w = o.z + v.z;
            reinterpret_cast<int4*>(g_off)[i] = o;
            reinterpret_cast<int4*>(g_cur)[i] = o;
        }
        int total = wsum[31];
        __syncthreads();
        if (t == 0) carry_s += total;
        __syncthreads();
    }
}

__global__ __launch_bounds__(256) void bucket_kernel(
    const int* __restrict__ src,
    const int* __restrict__ dst,
    const float* __restrict__ ew,
    int E)
{
    int i = blockIdx.x * blockDim.x + threadIdx.x;
    int stride = gridDim.x * blockDim.x;
    for (; i < E; i += stride) {
        int d = dst[i];
        int p = atomicAdd(&g_cur[d], 1);
        g_edge[p] = make_int2(src[i], __float_as_int(ew[i]));
    }
}

// ---------------------------------------------------------------------------
// Kernel 4: per-node fp16 gather-aggregate + fused ReLU.
// ---------------------------------------------------------------------------
__global__ __launch_bounds__(128) void aggregate_f16_kernel(
    const __half* __restrict__ hp,
    float* __restrict__ out,
    int N)
{
    const int sub = threadIdx.x >> 6;
    const int tt  = threadIdx.x & 63;
    const int n = blockIdx.x * 2 + sub;
    if (n >= N) return;
    const int col = tt * 8;

    int j  = g_off[n];
    const int je = g_cur[n];

    float a0[8] = {0.f,0.f,0.f,0.f,0.f,0.f,0.f,0.f};
    float a1[8] = {0.f,0.f,0.f,0.f,0.f,0.f,0.f,0.f};

    for (; j + 1 < je; j += 2) {
        int2 e0 = __ldg(&g_edge[j]);
        int2 e1 = __ldg(&g_edge[j + 1]);
        float w0 = __int_as_float(e0.y);
        float w1 = __int_as_float(e1.y);
        uint4 p0 = *reinterpret_cast<const uint4*>(hp + (size_t)e0.x * D + col);
        uint4 p1 = *reinterpret_cast<const uint4*>(hp + (size_t)e1.x * D + col);

        float2 f;
        f = __half22float2(*reinterpret_cast<__half2*>(&p0.x)); a0[0] += w0*f.x; a0[1] += w0*f.y;
        f = __half22float2(*reinterpret_cast<__half2*>(&p0.y)); a0[2] += w0*f.x; a0[3] += w0*f.y;
        f = __half22float2(*reinterpret_cast<__half2*>(&p0.z)); a0[4] += w0*f.x; a0[5] += w0*f.y;
        f = __half22float2(*reinterpret_cast<__half2*>(&p0.w)); a0[6] += w0*f.x; a0[7] += w0*f.y;
        f = __half22float2(*reinterpret_cast<__half2*>(&p1.x)); a1[0] += w1*f.x; a1[1] += w1*f.y;
        f = __half22float2(*reinterpret_cast<__half2*>(&p1.y)); a1[2] += w1*f.x; a1[3] += w1*f.y;
        f = __half22float2(*reinterpret_cast<__half2*>(&p1.z)); a1[4] += w1*f.x; a1[5] += w1*f.y;
        f = __half22float2(*reinterpret_cast<__half2*>(&p1.w)); a1[6] += w1*f.x; a1[7] += w1*f.y;
    }
    if (j < je) {
        int2 e0 = __ldg(&g_edge[j]);
        float w0 = __int_as_float(e0.y);
        uint4 p0 = *reinterpret_cast<const uint4*>(hp + (size_t)e0.x * D + col);
        float2 f;
        f = __half22float2(*reinterpret_cast<__half2*>(&p0.x)); a0[0] += w0*f.x; a0[1] += w0*f.y;
        f = __half22float2(*reinterpret_cast<__half2*>(&p0.y)); a0[2] += w0*f.x; a0[3] += w0*f.y;
        f = __half22float2(*reinterpret_cast<__half2*>(&p0.z)); a0[4] += w0*f.x; a0[5] += w0*f.y;
        f = __half22float2(*reinterpret_cast<__half2*>(&p0.w)); a0[6] += w0*f.x; a0[7] += w0*f.y;
    }

    float4 r0, r1;
    r0.x = fmaxf(a0[0] + a1[0], 0.f);
    r0.y = fmaxf(a0[1] + a1[1], 0.f);
    r0.z = fmaxf(a0[2] + a1[2], 0.f);
    r0.w = fmaxf(a0[3] + a1[3], 0.f);
    r1.x = fmaxf(a0[4] + a1[4], 0.f);
    r1.y = fmaxf(a0[5] + a1[5], 0.f);
    r1.z = fmaxf(a0[6] + a1[6], 0.f);
    r1.w = fmaxf(a0[7] + a1[7], 0.f);
    *reinterpret_cast<float4*>(out + (size_t)n * D + col)     = r0;
    *reinterpret_cast<float4*>(out + (size_t)n * D + col + 4) = r1;
}

// ---------------------------------------------------------------------------
// Launch — graph-parallel fork/join
// ---------------------------------------------------------------------------
extern "C" void kernel_launch(void* const* d_in, const int* in_sizes, int n_in,
                              void* d_out, int out_size)
{
    const float* h   = (const float*)d_in[0];
    const float* w   = (const float*)d_in[1];
    const float* ew  = (const float*)d_in[2];
    const int*   sv  = (const int*)d_in[3];
    const int*   dv  = (const int*)d_in[4];
    float* out       = (float*)d_out;

    const int M = in_sizes[0] / D;      // 100000
    const int E = in_sizes[2];          // 1600000

    static __half* hp  = nullptr;
    static __half* wf  = nullptr;
    static int*    cur = nullptr;
    static cudaStream_t s2 = nullptr;
    static cudaEvent_t ev_fork = nullptr, ev_join = nullptr;
    static bool attr_set = false;
    if (!hp)  cudaGetSymbolAddress((void**)&hp,  g_hp16);
    if (!wf)  cudaGetSymbolAddress((void**)&wf,  g_wf16);
    if (!cur) cudaGetSymbolAddress((void**)&cur, g_cur);
    if (!s2) {
        cudaStreamCreateWithFlags(&s2, cudaStreamNonBlocking);
        cudaEventCreateWithFlags(&ev_fork, cudaEventDisableTiming);
        cudaEventCreateWithFlags(&ev_join, cudaEventDisableTiming);
    }
    if (!attr_set) {
        cudaFuncSetAttribute(gemm_f16_kernel,
                             cudaFuncAttributeMaxDynamicSharedMemorySize, SMEM_GEMM_BYTES);
        attr_set = true;
    }

    // Fork
    cudaEventRecord(ev_fork, 0);
    cudaStreamWaitEvent(s2, ev_fork, 0);

    // Branch A (main): W conversion -> GEMM
    convert_w_kernel<<<(D * D + 255) / 256, 256>>>(w);
    dim3 ggrid((M + 127) / 128, D / 128);
    gemm_f16_kernel<<<ggrid, 256, SMEM_GEMM_BYTES>>>(h, wf, M);

    // Branch B (side): CSR build
    cudaMemsetAsync(cur, 0, (size_t)M * sizeof(int), s2);
    int eblocks = min((E + 255) / 256, 148 * 8);
    hist_kernel<<<eblocks, 256, 0, s2>>>(dv, E);
    scan_kernel<<<1, 1024, 0, s2>>>(M);
    bucket_kernel<<<eblocks, 256, 0, s2>>>(sv, dv, ew, E);

    // Join
    cudaEventRecord(ev_join, s2);
    cudaStreamWaitEvent(0, ev_join, 0);

    // Aggregate
    aggregate_f16_kernel<<<(M + 1) / 2, 128>>>(hp, out, M);
}